// round 1
// baseline (speedup 1.0000x reference)
#include <cuda_runtime.h>
#include <cstddef>

// Problem constants
constexpr int BB   = 8;      // batch
constexpr int TT   = 16;     // timesteps
constexpr int CIN  = 3;      // input channels
constexpr int HID  = 64;     // hidden channels
constexpr int CO4  = 256;    // 4 * HID (gates)
constexpr int HW   = 32;     // spatial
constexpr int NPIX = 1024;   // 32*32
constexpr int KK   = 49;     // 7*7

// Scratch (device globals; no allocation allowed)
__device__ float g_xg[(size_t)2 * BB * TT * CO4 * NPIX];   // input-conv gates, both dirs (268 MB)
__device__ float g_h[2][(size_t)2 * BB * HID * NPIX];      // ping-pong hidden state
__device__ float g_c[(size_t)2 * BB * HID * NPIX];         // cell state (in-place)

__device__ __forceinline__ float sigf(float x) {
    return __fdividef(1.0f, 1.0f + __expf(-x));
}
__device__ __forceinline__ float tanh_fast(float x) {
    return __fdividef(2.0f, 1.0f + __expf(-2.0f * x)) - 1.0f;
}

// ---------------------------------------------------------------------------
// Kernel 1: input-to-gate conv for ALL timesteps, both directions, bias folded.
// grid = 65536 blocks: bid -> {yb(4), cog(64), t(16), n(8), dir(2)}; 256 thr.
// Each thread: 4 consecutive out-channels at one pixel.
// ---------------------------------------------------------------------------
__global__ void input_conv_kernel(const float* __restrict__ x,
                                  const float* __restrict__ wf,
                                  const float* __restrict__ bf,
                                  const float* __restrict__ wb,
                                  const float* __restrict__ bb)
{
    int bid = blockIdx.x;
    int yb  = bid & 3;
    int cog = (bid >> 2) & 63;
    int t   = (bid >> 8) & 15;
    int n   = (bid >> 12) & 7;
    int dir = bid >> 15;

    int tid = threadIdx.x;
    int xc  = tid & 31;
    int yr  = tid >> 5;
    int y   = yb * 8 + yr;

    __shared__ float s_w[4 * 147];
    __shared__ float s_b[4];
    const float* w    = dir ? wb : wf;
    const float* bias = dir ? bb : bf;
    for (int i = tid; i < 588; i += 256) s_w[i] = w[cog * 588 + i];
    if (tid < 4) s_b[tid] = bias[cog * 4 + tid];
    __syncthreads();

    float a0 = s_b[0], a1 = s_b[1], a2 = s_b[2], a3 = s_b[3];
    const float* xin = x + (size_t)(n * TT + t) * CIN * NPIX;

    #pragma unroll
    for (int ci = 0; ci < CIN; ci++) {
        #pragma unroll
        for (int ky = 0; ky < 7; ky++) {
            int yy = y + ky - 3;
            if (yy < 0 || yy >= HW) continue;
            #pragma unroll
            for (int kx = 0; kx < 7; kx++) {
                int xx = xc + kx - 3;
                if (xx < 0 || xx >= HW) continue;
                float xv = xin[ci * NPIX + yy * 32 + xx];
                int widx = ci * 49 + ky * 7 + kx;
                a0 = fmaf(xv, s_w[widx],       a0);
                a1 = fmaf(xv, s_w[147 + widx], a1);
                a2 = fmaf(xv, s_w[294 + widx], a2);
                a3 = fmaf(xv, s_w[441 + widx], a3);
            }
        }
    }

    float* og = g_xg + (size_t)(((dir * BB + n) * TT + t) * CO4 + cog * 4) * NPIX
                      + y * 32 + xc;
    og[0]        = a0;
    og[NPIX]     = a1;
    og[2 * NPIX] = a2;
    og[3 * NPIX] = a3;
}

// ---------------------------------------------------------------------------
// Kernel 2: one recurrence step, BOTH directions in the same wave.
// grid = 256 blocks: bid -> {tile(4: 16x16 spatial), hg(4: 16 hid-ch), n(8), dir(2)}
// 256 threads: tid -> {co8(8), row(16), colh(2x8)}. Each thread accumulates
// 8 "m" channels (4 gates x 2 hid) x 8 pixels = 64 fp32 accumulators.
// Inner: hidden conv as smem-tiled GEMM over (ci chunk=2) x 7x7 taps.
// Epilogue: + precomputed xg, LSTM gates, write c, h(ping-pong), output.
// ---------------------------------------------------------------------------
__global__ __launch_bounds__(256, 2)
void lstm_step_kernel(const float* __restrict__ whf,
                      const float* __restrict__ whb,
                      float* __restrict__ out, int t)
{
    __shared__ float s_w[64 * 98];     // [m][ci2*49 + k], stride 98
    __shared__ float s_in[2 * 22 * 28]; // [ci2][row 22][col stride 28]

    int bid  = blockIdx.x;
    int tile = bid & 3;
    int hg   = (bid >> 2) & 3;
    int n    = (bid >> 4) & 7;
    int dir  = bid >> 7;
    int ty0  = (tile >> 1) * 16;
    int tx0  = (tile & 1) * 16;

    int tid  = threadIdx.x;
    int co8  = tid >> 5;        // 0..7 (warp-uniform)
    int gq   = tid & 31;
    int row  = gq >> 1;         // 0..15
    int colh = (gq & 1) * 8;    // 0 or 8

    const float* w = dir ? whb : whf;
    int rb = t & 1;
    const float* hread  = g_h[rb]     + (size_t)(dir * BB + n) * HID * NPIX;
    float*       hwrite = g_h[rb ^ 1] + (size_t)(dir * BB + n) * HID * NPIX;
    float*       cbuf   = g_c         + (size_t)(dir * BB + n) * HID * NPIX;

    float acc[8][8];
    #pragma unroll
    for (int j = 0; j < 8; j++)
        #pragma unroll
        for (int p = 0; p < 8; p++) acc[j][p] = 0.0f;

    if (t > 0) {
        for (int cib = 0; cib < HID; cib += 2) {
            // ---- load weight chunk: 64 m-channels x (2 ci x 49 taps) ----
            for (int i = tid; i < 64 * 98; i += 256) {
                int m = i / 98;
                int r = i - m * 98;
                int j    = m & 7;
                int co8m = m >> 3;
                int gate = j >> 1;
                int hcl  = j & 1;
                int co_act = gate * HID + hg * 16 + co8m * 2 + hcl;
                s_w[m * 98 + r] = w[(size_t)co_act * (HID * KK) + cib * 49 + r];
            }
            // ---- load input halo tile: 2 ci x 22 x 22 (zero-padded) ----
            for (int i = tid; i < 2 * 22 * 22; i += 256) {
                int ci2 = i / 484;
                int rem = i - ci2 * 484;
                int r   = rem / 22;
                int cc  = rem - r * 22;
                int yy = ty0 - 3 + r;
                int xx = tx0 - 3 + cc;
                float v = 0.0f;
                if (yy >= 0 && yy < HW && xx >= 0 && xx < HW)
                    v = hread[(size_t)(cib + ci2) * NPIX + yy * 32 + xx];
                s_in[(ci2 * 22 + r) * 28 + cc] = v;
            }
            __syncthreads();

            // ---- compute: 2 ci x 7 ky x 7 kx x (8 m x 8 px) FMAs ----
            #pragma unroll
            for (int ci2 = 0; ci2 < 2; ci2++) {
                #pragma unroll
                for (int ky = 0; ky < 7; ky++) {
                    const float* ir = &s_in[(ci2 * 22 + row + ky) * 28 + colh];
                    float inr[16];
                    float4 v0 = *(const float4*)(ir);
                    float4 v1 = *(const float4*)(ir + 4);
                    float4 v2 = *(const float4*)(ir + 8);
                    float4 v3 = *(const float4*)(ir + 12);
                    inr[0] = v0.x; inr[1] = v0.y; inr[2]  = v0.z; inr[3]  = v0.w;
                    inr[4] = v1.x; inr[5] = v1.y; inr[6]  = v1.z; inr[7]  = v1.w;
                    inr[8] = v2.x; inr[9] = v2.y; inr[10] = v2.z; inr[11] = v2.w;
                    inr[12] = v3.x; inr[13] = v3.y; inr[14] = v3.z; inr[15] = v3.w;
                    const float* wp = &s_w[(co8 * 8) * 98 + ci2 * 49 + ky * 7];
                    #pragma unroll
                    for (int kx = 0; kx < 7; kx++) {
                        float wv[8];
                        #pragma unroll
                        for (int j = 0; j < 8; j++) wv[j] = wp[j * 98 + kx];
                        #pragma unroll
                        for (int j = 0; j < 8; j++)
                            #pragma unroll
                            for (int p = 0; p < 8; p++)
                                acc[j][p] = fmaf(wv[j], inr[kx + p], acc[j][p]);
                    }
                }
            }
            __syncthreads();
        }
    }

    // ---- epilogue: gates + LSTM update + writes ----
    int tcur = dir ? (TT - 1 - t) : t;
    const float* xgp = g_xg + (size_t)(((dir * BB + n) * TT + tcur) * CO4) * NPIX;
    int y = ty0 + row;

    #pragma unroll
    for (int hcl = 0; hcl < 2; hcl++) {
        int hch = hg * 16 + co8 * 2 + hcl;
        #pragma unroll
        for (int p = 0; p < 8; p++) {
            int xx = tx0 + colh + p;
            int yx = y * 32 + xx;
            float ig = acc[0 + hcl][p] + xgp[(size_t)(0 * HID + hch) * NPIX + yx];
            float fg = acc[2 + hcl][p] + xgp[(size_t)(1 * HID + hch) * NPIX + yx];
            float gg = acc[4 + hcl][p] + xgp[(size_t)(2 * HID + hch) * NPIX + yx];
            float og = acc[6 + hcl][p] + xgp[(size_t)(3 * HID + hch) * NPIX + yx];
            float cp = (t > 0) ? cbuf[(size_t)hch * NPIX + yx] : 0.0f;
            float cn = sigf(fg) * cp + sigf(ig) * tanh_fast(gg);
            float hn = sigf(og) * tanh_fast(cn);
            cbuf[(size_t)hch * NPIX + yx]   = cn;
            hwrite[(size_t)hch * NPIX + yx] = hn;
            out[(size_t)((n * TT + tcur) * (2 * HID) + dir * HID + hch) * NPIX + yx] = hn;
        }
    }
}

// ---------------------------------------------------------------------------
// Launch: 1 input-conv kernel + 16 sequential recurrence kernels (graph-safe).
// ---------------------------------------------------------------------------
extern "C" void kernel_launch(void* const* d_in, const int* in_sizes, int n_in,
                              void* d_out, int out_size)
{
    const float* x      = (const float*)d_in[0];
    const float* w_ih_f = (const float*)d_in[1];
    const float* w_hh_f = (const float*)d_in[2];
    const float* b_f    = (const float*)d_in[3];
    const float* w_ih_b = (const float*)d_in[4];
    const float* w_hh_b = (const float*)d_in[5];
    const float* b_b    = (const float*)d_in[6];
    float* out = (float*)d_out;

    input_conv_kernel<<<65536, 256>>>(x, w_ih_f, b_f, w_ih_b, b_b);
    for (int t = 0; t < TT; t++)
        lstm_step_kernel<<<256, 256>>>(w_hh_f, w_hh_b, out, t);
}

// round 3
// speedup vs baseline: 2.4777x; 2.4777x over previous
#include <cuda_runtime.h>
#include <cstdint>
#include <cstddef>

// ---------------- problem constants ----------------
constexpr int BB   = 8;
constexpr int TT   = 16;
constexpr int CIN  = 3;
constexpr int HID  = 64;
constexpr int HW   = 32;
constexpr int NPIX = 1024;

// ---------------- step-kernel tiling ----------------
// CTA: M=128 (4 gates x 32 hid), N=256 px (8 rows x 32), K=3136 (64 ci x 49 taps)
constexpr int BST   = 68;            // B_s stride in words ([px][ci] padded)
constexpr int AST   = 68;            // A_s stride in words ([m][ci] padded)
constexpr int SGST  = 260;           // s_g stride (epilogue gate staging)
constexpr int BROWS = 14 * 32;       // 448 pixel-rows (8 out rows + 3 halo each side)
constexpr int B_WORDS = BROWS * BST;         // 30464
constexpr int A_WORDS = 128 * AST;           // 8704 per buffer
constexpr int SM_A_OFF = B_WORDS;            // word offset of A double buffer
constexpr size_t SMEM_BYTES = (size_t)(B_WORDS + 2 * A_WORDS) * 4;  // 191488

// ---------------- device scratch ----------------
__device__ float    g_xg[(size_t)2 * BB * TT * 256 * NPIX];  // input-conv gates (268 MB)
__device__ float    g_h[2][(size_t)2 * BB * HID * NPIX];     // ping-pong hidden
__device__ float    g_c[(size_t)2 * BB * HID * NPIX];        // cell state
__device__ uint32_t g_wA[(size_t)2 * 2 * 49 * 128 * 64];     // tf32 A tiles (6.4 MB)

// ---------------- helpers ----------------
__device__ __forceinline__ uint32_t smem_u32(const void* p) {
    uint32_t a;
    asm("{ .reg .u64 t; cvta.to.shared.u64 t, %1; cvt.u32.u64 %0, t; }" : "=r"(a) : "l"(p));
    return a;
}
__device__ __forceinline__ uint32_t f2tf32(float v) {
    uint32_t r;
    asm("cvt.rna.tf32.f32 %0, %1;" : "=r"(r) : "f"(v));
    return r;
}
__device__ __forceinline__ void mma_tf32(float* c, const uint32_t* a, const uint32_t* b) {
    asm volatile(
        "mma.sync.aligned.m16n8k8.row.col.f32.tf32.tf32.f32 "
        "{%0,%1,%2,%3}, {%4,%5,%6,%7}, {%8,%9}, {%0,%1,%2,%3};"
        : "+f"(c[0]), "+f"(c[1]), "+f"(c[2]), "+f"(c[3])
        : "r"(a[0]), "r"(a[1]), "r"(a[2]), "r"(a[3]), "r"(b[0]), "r"(b[1]));
}
__device__ __forceinline__ void cp16(uint32_t dst, const void* src) {
    asm volatile("cp.async.cg.shared.global [%0], [%1], 16;" :: "r"(dst), "l"(src));
}
__device__ __forceinline__ void cp_commit() {
    asm volatile("cp.async.commit_group;" ::: "memory");
}
__device__ __forceinline__ void cp_wait0() {
    asm volatile("cp.async.wait_group 0;" ::: "memory");
}
__device__ __forceinline__ float sigf(float x) {
    return __fdividef(1.0f, 1.0f + __expf(-x));
}
__device__ __forceinline__ float tanh_fast(float x) {
    return __fdividef(2.0f, 1.0f + __expf(-2.0f * x)) - 1.0f;
}

// ---------------------------------------------------------------------------
// Kernel 0: pre-transpose hidden weights to tf32 A tiles.
// g_wA[(dir*2+mblk)*49 + j][m=gate*32+hl][ci], taps ordered kx-major (kx=j/7).
// ---------------------------------------------------------------------------
__global__ void prep_w_kernel(const float* __restrict__ wf, const float* __restrict__ wb)
{
    int bid  = blockIdx.x;
    int j    = bid % 49;
    int mblk = (bid / 49) & 1;
    int dir  = bid / 98;
    int kx   = j / 7, ky = j % 7;
    const float* w = dir ? wb : wf;
    uint32_t* dst = g_wA + (size_t)bid * 8192;
    for (int i = threadIdx.x; i < 8192; i += 256) {
        int m = i >> 6, ci = i & 63;
        int gate = m >> 5, hl = m & 31;
        int co = gate * 64 + mblk * 32 + hl;
        float v = w[((size_t)co * HID + ci) * 49 + ky * 7 + kx];
        dst[i] = f2tf32(v);
    }
}

// ---------------------------------------------------------------------------
// Kernel 1: input-to-gate conv, all timesteps, both dirs, bias folded.
// ---------------------------------------------------------------------------
__global__ void input_conv_kernel(const float* __restrict__ x,
                                  const float* __restrict__ wf,
                                  const float* __restrict__ bf,
                                  const float* __restrict__ wb,
                                  const float* __restrict__ bb)
{
    int bid = blockIdx.x;
    int yb  = bid & 3;
    int cog = (bid >> 2) & 63;
    int t   = (bid >> 8) & 15;
    int n   = (bid >> 12) & 7;
    int dir = bid >> 15;

    int tid = threadIdx.x;
    int xc  = tid & 31;
    int yr  = tid >> 5;
    int y   = yb * 8 + yr;

    __shared__ float s_w[4 * 147];
    __shared__ float s_b[4];
    const float* w    = dir ? wb : wf;
    const float* bias = dir ? bb : bf;
    for (int i = tid; i < 588; i += 256) s_w[i] = w[cog * 588 + i];
    if (tid < 4) s_b[tid] = bias[cog * 4 + tid];
    __syncthreads();

    float a0 = s_b[0], a1 = s_b[1], a2 = s_b[2], a3 = s_b[3];
    const float* xin = x + (size_t)(n * TT + t) * CIN * NPIX;

    #pragma unroll
    for (int ci = 0; ci < CIN; ci++) {
        #pragma unroll
        for (int ky = 0; ky < 7; ky++) {
            int yy = y + ky - 3;
            if (yy < 0 || yy >= HW) continue;
            #pragma unroll
            for (int kx = 0; kx < 7; kx++) {
                int xx = xc + kx - 3;
                if (xx < 0 || xx >= HW) continue;
                float xv = xin[ci * NPIX + yy * 32 + xx];
                int widx = ci * 49 + ky * 7 + kx;
                a0 = fmaf(xv, s_w[widx],       a0);
                a1 = fmaf(xv, s_w[147 + widx], a1);
                a2 = fmaf(xv, s_w[294 + widx], a2);
                a3 = fmaf(xv, s_w[441 + widx], a3);
            }
        }
    }

    float* og = g_xg + (size_t)(((dir * BB + n) * TT + t) * 256 + cog * 4) * NPIX + y * 32 + xc;
    og[0]        = a0;
    og[NPIX]     = a1;
    og[2 * NPIX] = a2;
    og[3 * NPIX] = a3;
}

// ---------------------------------------------------------------------------
// Kernel 2: one recurrence step via mma.sync tf32 implicit conv-GEMM.
// grid 128 = nb(4) x mblk(2) x n(8) x dir(2); 512 threads (16 warps).
// ---------------------------------------------------------------------------
__global__ void __launch_bounds__(512, 1)
lstm_step_mma(float* __restrict__ out, int t)
{
    extern __shared__ char smem[];
    uint32_t* smw = (uint32_t*)smem;
    uint32_t  sb  = smem_u32(smem);

    int tid = threadIdx.x, wid = tid >> 5, lane = tid & 31;
    int rr = lane >> 2, cc = lane & 3;
    int wm = wid & 1;          // m half (64)
    int wn = wid >> 1;         // n block (32 px)

    int bid  = blockIdx.x;
    int nb   = bid & 3;
    int mblk = (bid >> 2) & 1;
    int n    = (bid >> 3) & 7;
    int dir  = (bid >> 6) & 1;
    int y0   = nb * 8;

    const float* hread  = g_h[t & 1]       + (size_t)(dir * BB + n) * HID * NPIX;
    float*       hwrite = g_h[(t & 1) ^ 1] + (size_t)(dir * BB + n) * HID * NPIX;
    float*       cbuf   = g_c              + (size_t)(dir * BB + n) * HID * NPIX;

    float acc[4][4][4];
    #pragma unroll
    for (int ms = 0; ms < 4; ms++)
        #pragma unroll
        for (int ns = 0; ns < 4; ns++)
            #pragma unroll
            for (int q = 0; q < 4; q++) acc[ms][ns][q] = 0.0f;

    auto stage_B = [&](int kx) {
        for (int jj = wid; jj < 896; jj += 16) {
            int cig = jj / 56;
            int rem = jj - cig * 56;
            int r   = rem >> 2;
            int xb  = (rem & 3) << 3;
            int ci  = cig * 4 + (lane >> 3);
            int x   = xb + (lane & 7);
            int yabs = y0 - 3 + r;
            int xs   = x + kx - 3;
            float v = 0.0f;
            if ((unsigned)yabs < 32u && (unsigned)xs < 32u)
                v = hread[ci * NPIX + yabs * 32 + xs];
            smw[(r * 32 + x) * BST + ci] = f2tf32(v);
        }
    };
    auto cpA = [&](int j, int buf) {
        const float4* src = (const float4*)(g_wA + (size_t)((dir * 2 + mblk) * 49 + j) * 8192);
        uint32_t dstb = sb + (uint32_t)(SM_A_OFF + buf * A_WORDS) * 4;
        #pragma unroll
        for (int q = 0; q < 4; q++) {
            int idx = q * 512 + tid;          // 0..2047
            int m = idx >> 4, c = idx & 15;
            cp16(dstb + (uint32_t)(m * AST + c * 4) * 4, src + idx);
        }
    };

    if (t > 0) {
        stage_B(0);
        cpA(0, 0);
        cp_commit();

        for (int j = 0; j < 49; j++) {
            int kx = j / 7, ky = j % 7;
            if (ky == 0 && j > 0) {
                __syncthreads();          // prior taps done reading B_s
                stage_B(kx);
            }
            cp_wait0();
            __syncthreads();              // A(j) + B staged visible to all
            if (j < 48) {
                cpA(j + 1, (j + 1) & 1);
                cp_commit();
            }

            // ---- compute tap j ----
            const uint32_t* As = smw + SM_A_OFF + (j & 1) * A_WORDS;
            const uint32_t* Aw = As + (wm * 64 + rr) * AST + cc;
            const uint32_t* Bw = smw + (wn * 32 + rr + ky * 32) * BST + cc;
            #pragma unroll
            for (int kc = 0; kc < 8; kc++) {
                int k0 = kc * 8;
                uint32_t a[4][4], b[4][2];
                #pragma unroll
                for (int ms = 0; ms < 4; ms++) {
                    const uint32_t* p = Aw + ms * 16 * AST + k0;
                    a[ms][0] = p[0];
                    a[ms][1] = p[8 * AST];
                    a[ms][2] = p[4];
                    a[ms][3] = p[8 * AST + 4];
                }
                #pragma unroll
                for (int ns = 0; ns < 4; ns++) {
                    const uint32_t* p = Bw + ns * 8 * BST + k0;
                    b[ns][0] = p[0];
                    b[ns][1] = p[4];
                }
                #pragma unroll
                for (int ms = 0; ms < 4; ms++)
                    #pragma unroll
                    for (int ns = 0; ns < 4; ns++)
                        mma_tf32(acc[ms][ns], a[ms], b[ns]);
            }
        }
        __syncthreads();   // all compute done before overwriting smem with s_g

        // ---- acc -> s_g gate staging ----
        float* sg = (float*)smem;
        #pragma unroll
        for (int ms = 0; ms < 4; ms++) {
            int m = wm * 64 + ms * 16 + rr;
            #pragma unroll
            for (int ns = 0; ns < 4; ns++) {
                int nn = wn * 32 + ns * 8 + 2 * cc;
                float2 v0 = make_float2(acc[ms][ns][0], acc[ms][ns][1]);
                float2 v1 = make_float2(acc[ms][ns][2], acc[ms][ns][3]);
                *(float2*)(sg + m * SGST + nn)       = v0;
                *(float2*)(sg + (m + 8) * SGST + nn) = v1;
            }
        }
        __syncthreads();
    }

    // ---- LSTM epilogue ----
    int tcur = dir ? (TT - 1 - t) : t;
    const float* xgp = g_xg + (size_t)(((dir * BB + n) * TT + tcur) * 256) * NPIX;
    const float* sg  = (const float*)smem;
    int hl  = tid >> 4;          // 0..31
    int px0 = (tid & 15) * 16;
    int hch = mblk * 32 + hl;

    #pragma unroll
    for (int p = 0; p < 16; p++) {
        int px = px0 + p;
        int yx = y0 * 32 + px;
        float hi = 0, hf = 0, hgg = 0, ho = 0;
        if (t > 0) {
            hi  = sg[(0 * 32 + hl) * SGST + px];
            hf  = sg[(1 * 32 + hl) * SGST + px];
            hgg = sg[(2 * 32 + hl) * SGST + px];
            ho  = sg[(3 * 32 + hl) * SGST + px];
        }
        float ig = hi  + xgp[(size_t)(0 * 64 + hch) * NPIX + yx];
        float fg = hf  + xgp[(size_t)(1 * 64 + hch) * NPIX + yx];
        float gg = hgg + xgp[(size_t)(2 * 64 + hch) * NPIX + yx];
        float og = ho  + xgp[(size_t)(3 * 64 + hch) * NPIX + yx];
        float cp = (t > 0) ? cbuf[(size_t)hch * NPIX + yx] : 0.0f;
        float cn = sigf(fg) * cp + sigf(ig) * tanh_fast(gg);
        float hn = sigf(og) * tanh_fast(cn);
        cbuf[(size_t)hch * NPIX + yx]   = cn;
        hwrite[(size_t)hch * NPIX + yx] = hn;
        out[(size_t)((n * TT + tcur) * (2 * HID) + dir * HID + hch) * NPIX + yx] = hn;
    }
}

// ---------------------------------------------------------------------------
extern "C" void kernel_launch(void* const* d_in, const int* in_sizes, int n_in,
                              void* d_out, int out_size)
{
    const float* x      = (const float*)d_in[0];
    const float* w_ih_f = (const float*)d_in[1];
    const float* w_hh_f = (const float*)d_in[2];
    const float* b_f    = (const float*)d_in[3];
    const float* w_ih_b = (const float*)d_in[4];
    const float* w_hh_b = (const float*)d_in[5];
    const float* b_b    = (const float*)d_in[6];
    float* out = (float*)d_out;

    cudaFuncSetAttribute(lstm_step_mma, cudaFuncAttributeMaxDynamicSharedMemorySize,
                         (int)SMEM_BYTES);

    prep_w_kernel<<<196, 256>>>(w_hh_f, w_hh_b);
    input_conv_kernel<<<65536, 256>>>(x, w_ih_f, b_f, w_ih_b, b_b);
    for (int t = 0; t < TT; t++)
        lstm_step_mma<<<128, 512, SMEM_BYTES>>>(out, t);
}

// round 4
// speedup vs baseline: 4.5708x; 1.8448x over previous
#include <cuda_runtime.h>
#include <cuda_fp16.h>
#include <cstdint>
#include <cstddef>

// ---------------- problem constants ----------------
constexpr int BB   = 8;
constexpr int TT   = 16;
constexpr int CIN  = 3;
constexpr int HID  = 64;
constexpr int HW   = 32;
constexpr int NPIX = 1024;

// ---------------- step-kernel tiling ----------------
// CTA: M=128 (4 gates x 32 hid), N=256 px (8 rows x 32), K=3136 (64 ci x 49 taps)
// B smem: [kc(4)][px(448)][8 words], word = half2 of ci pair (in-chunk permuted)
constexpr int B_WORDS   = 4 * 448 * 8;        // 14336
constexpr int SM_A_WORD = B_WORDS;            // A ring: 4 buffers x 4096 words (fp16 frags)
constexpr int A_WORDS   = 4096;               // 16KB per tap tile
constexpr int SGST      = 260;                // epilogue gate staging stride (floats)
constexpr size_t SMEM_BYTES = (size_t)128 * SGST * 4;  // 133120 (>= B+A ring = 122880)

// ---------------- device scratch ----------------
__device__ float    g_xg[(size_t)2 * BB * TT * 256 * NPIX];  // input-conv gates (268 MB)
__device__ float    g_h[2][(size_t)2 * BB * HID * NPIX];     // ping-pong hidden
__device__ float    g_c[(size_t)2 * BB * HID * NPIX];        // cell state
__device__ uint32_t g_wA[(size_t)2 * 2 * 49 * A_WORDS];      // fp16 A fragment tiles (3.2 MB)

// ---------------- helpers ----------------
__device__ __forceinline__ uint32_t smem_u32(const void* p) {
    uint32_t a;
    asm("{ .reg .u64 t; cvta.to.shared.u64 t, %1; cvt.u32.u64 %0, t; }" : "=r"(a) : "l"(p));
    return a;
}
__device__ __forceinline__ void mma_f16(float* c, const uint32_t* a, const uint32_t* b) {
    asm volatile(
        "mma.sync.aligned.m16n8k16.row.col.f32.f16.f16.f32 "
        "{%0,%1,%2,%3}, {%4,%5,%6,%7}, {%8,%9}, {%0,%1,%2,%3};"
        : "+f"(c[0]), "+f"(c[1]), "+f"(c[2]), "+f"(c[3])
        : "r"(a[0]), "r"(a[1]), "r"(a[2]), "r"(a[3]), "r"(b[0]), "r"(b[1]));
}
__device__ __forceinline__ void cp16(uint32_t dst, const void* src) {
    asm volatile("cp.async.cg.shared.global [%0], [%1], 16;" :: "r"(dst), "l"(src));
}
__device__ __forceinline__ void cp_commit() {
    asm volatile("cp.async.commit_group;" ::: "memory");
}
__device__ __forceinline__ void cp_wait2() {
    asm volatile("cp.async.wait_group 2;" ::: "memory");
}
__device__ __forceinline__ uint32_t packh2(float lo, float hi) {
    __half2 h = __floats2half2_rn(lo, hi);
    return *(uint32_t*)&h;
}
__device__ __forceinline__ float sigf(float x) {
    return __fdividef(1.0f, 1.0f + __expf(-x));
}
__device__ __forceinline__ float tanh_fast(float x) {
    return __fdividef(2.0f, 1.0f + __expf(-2.0f * x)) - 1.0f;
}

// ---------------------------------------------------------------------------
// Kernel 0: hidden weights -> fp16 A-fragment tiles.
// g_wA[(dir*2+mblk)*49 + j]: word i = [kc(4)][mtile(8)][lane(32)][reg(4)],
// reg r: m = mt*16 + (lane>>2) + (r&1)*8, k-pair = kc*16 + (lane&3)*2 + (r>>1)*8.
// ---------------------------------------------------------------------------
__global__ void prep_w_kernel(const float* __restrict__ wf, const float* __restrict__ wb)
{
    int bid  = blockIdx.x;
    int j    = bid % 49;
    int mblk = (bid / 49) & 1;
    int dir  = bid / 98;
    int kx   = j / 7, ky = j % 7;
    const float* w = dir ? wb : wf;
    uint32_t* dst = g_wA + (size_t)bid * A_WORDS;
    for (int i = threadIdx.x; i < A_WORDS; i += 256) {
        int reg  = i & 3;
        int lane = (i >> 2) & 31;
        int mt   = (i >> 7) & 7;
        int kc   = i >> 10;
        int m = mt * 16 + (lane >> 2) + (reg & 1) * 8;
        int k = kc * 16 + (lane & 3) * 2 + (reg >> 1) * 8;
        int gate = m >> 5, hl = m & 31;
        int co = gate * 64 + mblk * 32 + hl;
        float lo = w[((size_t)co * HID + k)     * 49 + ky * 7 + kx];
        float hi = w[((size_t)co * HID + k + 1) * 49 + ky * 7 + kx];
        dst[i] = packh2(lo, hi);
    }
}

// ---------------------------------------------------------------------------
// Kernel 1: input-to-gate conv, smem-tiled, both dirs share the x tile.
// grid 4096 = cg(32: 8 gate-ch x 2 dirs) x t(16) x n(8); 256 threads.
// ---------------------------------------------------------------------------
__global__ void __launch_bounds__(256)
input_conv_kernel(const float* __restrict__ x,
                  const float* __restrict__ wf,
                  const float* __restrict__ bf,
                  const float* __restrict__ wb,
                  const float* __restrict__ bb)
{
    __shared__ float sx[3 * 38 * 40];
    __shared__ float sw[16 * 147];
    __shared__ float sbias[16];

    int bid = blockIdx.x;
    int cg  = bid & 31;
    int t   = (bid >> 5) & 15;
    int n   = bid >> 9;
    int tid = threadIdx.x;

    const float* xin = x + (size_t)(n * TT + t) * CIN * NPIX;
    for (int i = tid; i < 3 * 38 * 38; i += 256) {
        int ci  = i / 1444;
        int rem = i - ci * 1444;
        int r   = rem / 38;
        int c   = rem - r * 38;
        int yy = r - 3, xx = c - 3;
        float v = ((unsigned)yy < 32u && (unsigned)xx < 32u)
                    ? xin[ci * NPIX + yy * 32 + xx] : 0.0f;
        sx[(ci * 38 + r) * 40 + c] = v;
    }
    for (int i = tid; i < 16 * 147; i += 256) {
        int m = i / 147, tap = i - m * 147;
        int dirm = m >> 3;
        int co = cg * 8 + (m & 7);
        const float* w = dirm ? wb : wf;
        sw[m * 147 + tap] = w[(size_t)co * 147 + tap];
    }
    if (tid < 16) {
        int dirm = tid >> 3;
        int co = cg * 8 + (tid & 7);
        sbias[tid] = (dirm ? bb : bf)[co];
    }
    __syncthreads();

    float acc[16][4];
    #pragma unroll
    for (int m = 0; m < 16; m++)
        #pragma unroll
        for (int pp = 0; pp < 4; pp++) acc[m][pp] = sbias[m];

    int xi = tid & 31;
    int y0 = tid >> 5;   // px = tid + pp*256 -> y = y0 + pp*8

    #pragma unroll 1
    for (int tap = 0; tap < 147; tap++) {
        int ci = tap / 49;
        int r2 = tap - ci * 49;
        int ky = r2 / 7;
        int kx = r2 - ky * 7;
        float wv[16];
        #pragma unroll
        for (int m = 0; m < 16; m++) wv[m] = sw[m * 147 + tap];
        #pragma unroll
        for (int pp = 0; pp < 4; pp++) {
            float xv = sx[(ci * 38 + y0 + pp * 8 + ky) * 40 + xi + kx];
            #pragma unroll
            for (int m = 0; m < 16; m++)
                acc[m][pp] = fmaf(xv, wv[m], acc[m][pp]);
        }
    }

    #pragma unroll
    for (int m = 0; m < 16; m++) {
        int dirm = m >> 3;
        int co = cg * 8 + (m & 7);
        float* og = g_xg + ((size_t)((dirm * BB + n) * TT + t) * 256 + co) * NPIX;
        #pragma unroll
        for (int pp = 0; pp < 4; pp++) og[tid + pp * 256] = acc[m][pp];
    }
}

// ---------------------------------------------------------------------------
// Kernel 2: one recurrence step via mma.sync fp16 (m16n8k16) implicit conv-GEMM.
// grid 128 = nb(4) x mblk(2) x n(8) x dir(2); 512 threads (16 warps).
// ---------------------------------------------------------------------------
__global__ void __launch_bounds__(512, 1)
lstm_step_mma(float* __restrict__ out, int t)
{
    extern __shared__ char smem[];
    uint32_t* smw = (uint32_t*)smem;
    uint32_t  sb  = smem_u32(smem);

    int tid = threadIdx.x, wid = tid >> 5, lane = tid & 31;
    int rr = lane >> 2, cc = lane & 3;
    int wm = wid & 1;          // m half (64)
    int wn = wid >> 1;         // n block (32 px)

    int bid  = blockIdx.x;
    int nb   = bid & 3;
    int mblk = (bid >> 2) & 1;
    int n    = (bid >> 3) & 7;
    int dir  = (bid >> 6) & 1;
    int y0   = nb * 8;

    const float* hread  = g_h[t & 1]       + (size_t)(dir * BB + n) * HID * NPIX;
    float*       hwrite = g_h[(t & 1) ^ 1] + (size_t)(dir * BB + n) * HID * NPIX;
    float*       cbuf   = g_c              + (size_t)(dir * BB + n) * HID * NPIX;

    float acc[4][4][4];
    #pragma unroll
    for (int ms = 0; ms < 4; ms++)
        #pragma unroll
        for (int ns = 0; ns < 4; ns++)
            #pragma unroll
            for (int q = 0; q < 4; q++) acc[ms][ns][q] = 0.0f;

    // B staging: word = half2(ci=2q, ci=2q+1) at [kc][px][pos], pos=(q&3)*2+(q&4?1:0)
    auto stage_B = [&](int kx) {
        for (int jj = wid; jj < 448; jj += 16) {
            int qg  = jj / 56;
            int rem = jj - qg * 56;
            int r   = rem >> 2;
            int xb  = (rem & 3) << 3;
            int q   = qg * 4 + (lane >> 3);
            int x   = xb + (lane & 7);
            int yabs = y0 - 3 + r;
            int xs   = x + kx - 3;
            float lo = 0.0f, hi = 0.0f;
            if ((unsigned)yabs < 32u && (unsigned)xs < 32u) {
                int off = yabs * 32 + xs;
                lo = hread[(2 * q) * NPIX + off];
                hi = hread[(2 * q + 1) * NPIX + off];
            }
            int kc = q >> 3, qq = q & 7;
            int pos = (qq & 3) * 2 + (qq >> 2);
            smw[kc * 3584 + (r * 32 + x) * 8 + pos] = packh2(lo, hi);
        }
    };
    auto cpA = [&](int j, int buf) {
        const float4* src = (const float4*)(g_wA + (size_t)((dir * 2 + mblk) * 49 + j) * A_WORDS);
        uint32_t dstb = sb + (uint32_t)(SM_A_WORD + buf * A_WORDS) * 4;
        cp16(dstb + tid * 16, src + tid);
        cp16(dstb + (tid + 512) * 16, src + tid + 512);
    };

    if (t > 0) {
        stage_B(0);
        cpA(0, 0); cp_commit();
        cpA(1, 1); cp_commit();
        cpA(2, 2); cp_commit();
        __syncthreads();

        for (int j = 0; j < 49; j++) {
            int kx = j / 7, ky = j % 7;
            if (ky == 0 && j > 0) {
                __syncthreads();      // prior kx done reading B
                stage_B(kx);
            }
            cp_wait2();
            __syncthreads();          // A(j) + B(kx) visible to all warps
            if (j + 3 < 49) { cpA(j + 3, (j + 3) & 3); cp_commit(); }

            const uint32_t* As = smw + SM_A_WORD + (j & 3) * A_WORDS;
            #pragma unroll
            for (int kc = 0; kc < 4; kc++) {
                uint4 a[4];
                uint2 b[4];
                #pragma unroll
                for (int ms = 0; ms < 4; ms++)
                    a[ms] = *(const uint4*)(As + ((kc * 8 + wm * 4 + ms) * 32 + lane) * 4);
                #pragma unroll
                for (int ns = 0; ns < 4; ns++)
                    b[ns] = *(const uint2*)(smw + kc * 3584 +
                              (wn * 32 + ns * 8 + rr + ky * 32) * 8 + cc * 2);
                #pragma unroll
                for (int ms = 0; ms < 4; ms++)
                    #pragma unroll
                    for (int ns = 0; ns < 4; ns++)
                        mma_f16(acc[ms][ns], (const uint32_t*)&a[ms], (const uint32_t*)&b[ns]);
            }
        }
        __syncthreads();   // all compute done before overwriting smem with s_g

        // ---- acc -> s_g gate staging ----
        float* sg = (float*)smem;
        #pragma unroll
        for (int ms = 0; ms < 4; ms++) {
            int m = wm * 64 + ms * 16 + rr;
            #pragma unroll
            for (int ns = 0; ns < 4; ns++) {
                int nn = wn * 32 + ns * 8 + 2 * cc;
                *(float2*)(sg + m * SGST + nn)       = make_float2(acc[ms][ns][0], acc[ms][ns][1]);
                *(float2*)(sg + (m + 8) * SGST + nn) = make_float2(acc[ms][ns][2], acc[ms][ns][3]);
            }
        }
        __syncthreads();
    }

    // ---- LSTM epilogue ----
    int tcur = dir ? (TT - 1 - t) : t;
    const float* xgp = g_xg + (size_t)(((dir * BB + n) * TT + tcur) * 256) * NPIX;
    const float* sg  = (const float*)smem;
    int hl  = tid >> 4;          // 0..31
    int px0 = (tid & 15) * 16;
    int hch = mblk * 32 + hl;

    #pragma unroll
    for (int p = 0; p < 16; p++) {
        int px = px0 + p;
        int yx = y0 * 32 + px;
        float hi = 0, hf = 0, hgg = 0, ho = 0;
        if (t > 0) {
            hi  = sg[(0 * 32 + hl) * SGST + px];
            hf  = sg[(1 * 32 + hl) * SGST + px];
            hgg = sg[(2 * 32 + hl) * SGST + px];
            ho  = sg[(3 * 32 + hl) * SGST + px];
        }
        float ig = hi  + xgp[(size_t)(0 * 64 + hch) * NPIX + yx];
        float fg = hf  + xgp[(size_t)(1 * 64 + hch) * NPIX + yx];
        float gg = hgg + xgp[(size_t)(2 * 64 + hch) * NPIX + yx];
        float og = ho  + xgp[(size_t)(3 * 64 + hch) * NPIX + yx];
        float cp = (t > 0) ? cbuf[(size_t)hch * NPIX + yx] : 0.0f;
        float cn = sigf(fg) * cp + sigf(ig) * tanh_fast(gg);
        float hn = sigf(og) * tanh_fast(cn);
        cbuf[(size_t)hch * NPIX + yx]   = cn;
        hwrite[(size_t)hch * NPIX + yx] = hn;
        out[(size_t)((n * TT + tcur) * (2 * HID) + dir * HID + hch) * NPIX + yx] = hn;
    }
}

// ---------------------------------------------------------------------------
extern "C" void kernel_launch(void* const* d_in, const int* in_sizes, int n_in,
                              void* d_out, int out_size)
{
    const float* x      = (const float*)d_in[0];
    const float* w_ih_f = (const float*)d_in[1];
    const float* w_hh_f = (const float*)d_in[2];
    const float* b_f    = (const float*)d_in[3];
    const float* w_ih_b = (const float*)d_in[4];
    const float* w_hh_b = (const float*)d_in[5];
    const float* b_b    = (const float*)d_in[6];
    float* out = (float*)d_out;

    cudaFuncSetAttribute(lstm_step_mma, cudaFuncAttributeMaxDynamicSharedMemorySize,
                         (int)SMEM_BYTES);

    prep_w_kernel<<<196, 256>>>(w_hh_f, w_hh_b);
    input_conv_kernel<<<4096, 256>>>(x, w_ih_f, b_f, w_ih_b, b_b);
    for (int t = 0; t < TT; t++)
        lstm_step_mma<<<128, 512, SMEM_BYTES>>>(out, t);
}

// round 6
// speedup vs baseline: 6.0557x; 1.3249x over previous
#include <cuda_runtime.h>
#include <cuda_fp16.h>
#include <cstdint>
#include <cstddef>

// ---------------- problem constants ----------------
constexpr int BB   = 8;
constexpr int TT   = 16;
constexpr int CIN  = 3;
constexpr int HID  = 64;
constexpr int NPIX = 1024;

// ---------------- step-kernel smem layout (words) ----------------
// B: [kcp(2)][px 532 = 14 rows x 38 cols][16 half2-words], stride 16 words/px
constexpr int B_KCP_W  = 532 * 16;          // 8512
constexpr int B_W      = 2 * B_KCP_W;       // 17024
constexpr int SM_A_W   = B_W;               // A ring: 3 buffers x 3 taps x 4096 words
constexpr int TAPBUF_W = 3 * 4096;          // 12288
constexpr size_t SMEM_STEP = (size_t)(B_W + 3 * TAPBUF_W) * 4;   // 215552 B
constexpr int SGST = 260;                   // epilogue gate staging stride (floats)

// ---------------- input-conv smem layout (words) ----------------
constexpr int SX2_PX  = 1520;               // 38x38 = 1444 real + zero pad (tap overreach)
constexpr int SM_WI_W = SX2_PX * 2;         // 3040
constexpr size_t SMEM_IC = (size_t)128 * SGST * 4;   // 133120 (>= 3040+13312 words)

// tap offset table: poff[j] = (j/7)*38 + j%7  (j up to 51 for padded taps)
__device__ __constant__ int c_poff[52] = {
      0,  1,  2,  3,  4,  5,  6,
     38, 39, 40, 41, 42, 43, 44,
     76, 77, 78, 79, 80, 81, 82,
    114,115,116,117,118,119,120,
    152,153,154,155,156,157,158,
    190,191,192,193,194,195,196,
    228,229,230,231,232,233,234,
    266,267,268};

// ---------------- device scratch ----------------
__device__ float    g_xg[(size_t)2 * BB * TT * 256 * NPIX];  // input-conv gates (268 MB)
__device__ float    g_h[2][(size_t)2 * BB * HID * NPIX];     // ping-pong hidden
__device__ float    g_c[(size_t)2 * BB * HID * NPIX];        // cell state
__device__ uint32_t g_wA[(size_t)2 * 2 * 52 * 4096];         // hidden-W fp16 frag tiles
__device__ uint32_t g_wI[(size_t)2 * 2 * 13 * 1024];         // input-W fp16 frag tiles

// ---------------- helpers ----------------
__device__ __forceinline__ uint32_t smem_u32(const void* p) {
    uint32_t a;
    asm("{ .reg .u64 t; cvta.to.shared.u64 t, %1; cvt.u32.u64 %0, t; }" : "=r"(a) : "l"(p));
    return a;
}
__device__ __forceinline__ void mma_f16(float* c, const uint32_t* a, const uint32_t* b) {
    asm volatile(
        "mma.sync.aligned.m16n8k16.row.col.f32.f16.f16.f32 "
        "{%0,%1,%2,%3}, {%4,%5,%6,%7}, {%8,%9}, {%0,%1,%2,%3};"
        : "+f"(c[0]), "+f"(c[1]), "+f"(c[2]), "+f"(c[3])
        : "r"(a[0]), "r"(a[1]), "r"(a[2]), "r"(a[3]), "r"(b[0]), "r"(b[1]));
}
__device__ __forceinline__ void cp16(uint32_t dst, const void* src) {
    asm volatile("cp.async.cg.shared.global [%0], [%1], 16;" :: "r"(dst), "l"(src));
}
__device__ __forceinline__ void cp_commit() {
    asm volatile("cp.async.commit_group;" ::: "memory");
}
__device__ __forceinline__ void cp_wait0() {
    asm volatile("cp.async.wait_group 0;" ::: "memory");
}
__device__ __forceinline__ void cp_wait1() {
    asm volatile("cp.async.wait_group 1;" ::: "memory");
}
__device__ __forceinline__ uint32_t packh2(float lo, float hi) {
    __half2 h = __floats2half2_rn(lo, hi);
    return *(uint32_t*)&h;
}
__device__ __forceinline__ float sigf(float x) {
    return __fdividef(1.0f, 1.0f + __expf(-x));
}
__device__ __forceinline__ float tanh_fast(float x) {
    return __fdividef(2.0f, 1.0f + __expf(-2.0f * x)) - 1.0f;
}

// ---------------------------------------------------------------------------
// Kernel 0a: hidden weights -> fp16 A-fragment tiles (52 taps, 49..51 zero).
// word i in tile = [kc(4)][mt(8)][lane(32)][reg(4)];
//   m = mt*16 + (lane>>2) + (reg&1)*8;  k = kc*16 + (lane&3)*2 + (reg>>1)*8.
// ---------------------------------------------------------------------------
__global__ void prep_w_kernel(const float* __restrict__ wf, const float* __restrict__ wb)
{
    int bid  = blockIdx.x;
    int j    = bid % 52;
    int mblk = (bid / 52) & 1;
    int dir  = bid / 104;
    const float* w = dir ? wb : wf;
    uint32_t* dst = g_wA + (size_t)bid * 4096;
    int valid = (j < 49);
    int ky = j / 7, kx = j - ky * 7;
    for (int i = threadIdx.x; i < 4096; i += 256) {
        int reg  = i & 3;
        int lane = (i >> 2) & 31;
        int mt   = (i >> 7) & 7;
        int kc   = i >> 10;
        int m = mt * 16 + (lane >> 2) + (reg & 1) * 8;
        int k = kc * 16 + (lane & 3) * 2 + (reg >> 1) * 8;
        int gate = m >> 5, hl = m & 31;
        int co = gate * 64 + mblk * 32 + hl;
        float lo = 0.0f, hi = 0.0f;
        if (valid) {
            lo = w[((size_t)co * HID + k)     * 49 + ky * 7 + kx];
            hi = w[((size_t)co * HID + k + 1) * 49 + ky * 7 + kx];
        }
        dst[i] = packh2(lo, hi);
    }
}

// ---------------------------------------------------------------------------
// Kernel 0b: input weights -> fp16 A-fragment tiles.
// K order: k = tap*4 + ci (ci slot 3 = zero), 13 chunks of 16 (taps >=49 zero).
// ---------------------------------------------------------------------------
__global__ void prep_wi_kernel(const float* __restrict__ wf, const float* __restrict__ wb)
{
    int bid   = blockIdx.x;
    int chunk = bid % 13;
    int mblk  = (bid / 13) & 1;
    int dir   = bid / 26;
    const float* w = dir ? wb : wf;
    uint32_t* dst = g_wI + (size_t)bid * 1024;
    for (int i = threadIdx.x; i < 1024; i += 256) {
        int reg  = i & 3;
        int lane = (i >> 2) & 31;
        int mt   = i >> 7;
        int m  = mt * 16 + (lane >> 2) + (reg & 1) * 8;
        int qq = (lane & 3) + (reg >> 1) * 4;
        int j  = chunk * 4 + (qq >> 1);
        int cp = qq & 1;
        int co = mblk * 128 + m;
        float lo = 0.0f, hi = 0.0f;
        if (j < 49) {
            int ky = j / 7, kx = j - ky * 7;
            int ci0 = cp * 2;
            lo = w[((size_t)co * CIN + ci0) * 49 + ky * 7 + kx];
            if (ci0 + 1 < CIN)
                hi = w[((size_t)co * CIN + ci0 + 1) * 49 + ky * 7 + kx];
        }
        dst[i] = packh2(lo, hi);
    }
}

// ---------------------------------------------------------------------------
// Kernel 1: input-to-gate conv via fp16 mma (bias folded).
// grid 2048 = nb(4) x mblk(2) x t(16) x n(8) x dir(2); 512 threads.
// ---------------------------------------------------------------------------
__global__ void __launch_bounds__(512, 1)
input_conv_tc(const float* __restrict__ x,
              const float* __restrict__ bf,
              const float* __restrict__ bb)
{
    extern __shared__ char smem[];
    uint32_t* smw = (uint32_t*)smem;
    uint32_t  sb  = smem_u32(smem);

    int tid = threadIdx.x, wid = tid >> 5, lane = tid & 31;
    int rr = lane >> 2, cc = lane & 3;
    int wm = wid & 1, wn = wid >> 1;

    int bid  = blockIdx.x;
    int nb   = bid & 3;
    int mblk = (bid >> 2) & 1;
    int t    = (bid >> 3) & 15;
    int n    = (bid >> 7) & 7;
    int dir  = bid >> 10;
    int y0   = nb * 8;

    // ---- stage x tile (38x38 + zero pad) as half2 pairs ----
    const float* xin = x + (size_t)(n * TT + t) * CIN * NPIX;
    for (int idx = tid; idx < SX2_PX; idx += 512) {
        float v0 = 0, v1 = 0, v2 = 0;
        if (idx < 1444) {
            int r = idx / 38, c = idx - r * 38;
            int ys = r - 3, xs = c - 3;
            if ((unsigned)ys < 32u && (unsigned)xs < 32u) {
                int o = ys * 32 + xs;
                v0 = xin[o]; v1 = xin[NPIX + o]; v2 = xin[2 * NPIX + o];
            }
        }
        smw[idx * 2]     = packh2(v0, v1);
        smw[idx * 2 + 1] = packh2(v2, 0.0f);
    }
    // ---- stage A (13 chunks) ----
    const float4* srcA = (const float4*)(g_wI + (size_t)(dir * 2 + mblk) * 13 * 1024);
    #pragma unroll
    for (int u = 0; u < 7; u++) {
        int i = u * 512 + tid;
        if (i < 3328) cp16(sb + (uint32_t)(SM_WI_W + i * 4) * 4, srcA + i);
    }
    cp_commit();
    cp_wait0();
    __syncthreads();

    float acc[4][4][4];
    #pragma unroll
    for (int ms = 0; ms < 4; ms++)
        #pragma unroll
        for (int ns = 0; ns < 4; ns++)
            #pragma unroll
            for (int q = 0; q < 4; q++) acc[ms][ns][q] = 0.0f;

    const uint32_t* As = smw + SM_WI_W;
    int pb = ((y0 + wn) * 38 + rr) * 2 + (cc & 1);   // word addr base into sx2

    #pragma unroll
    for (int ch = 0; ch < 13; ch++) {
        int j1 = ch * 4 + (cc >> 1);
        int o1 = c_poff[j1] * 2;
        int o2 = c_poff[j1 + 2] * 2;
        uint32_t b[4][2];
        #pragma unroll
        for (int ns = 0; ns < 4; ns++) {
            b[ns][0] = smw[pb + o1 + ns * 16];
            b[ns][1] = smw[pb + o2 + ns * 16];
        }
        uint4 a4[4];
        #pragma unroll
        for (int ms = 0; ms < 4; ms++)
            a4[ms] = *(const uint4*)(As + ch * 1024 + (wm * 4 + ms) * 128 + lane * 4);
        #pragma unroll
        for (int ms = 0; ms < 4; ms++)
            #pragma unroll
            for (int ns = 0; ns < 4; ns++)
                mma_f16(acc[ms][ns], (const uint32_t*)&a4[ms], b[ns]);
    }
    __syncthreads();

    // ---- acc -> s_g -> coalesced global write (+bias) ----
    float* sg = (float*)smem;
    #pragma unroll
    for (int ms = 0; ms < 4; ms++) {
        int m = wm * 64 + ms * 16 + rr;
        #pragma unroll
        for (int ns = 0; ns < 4; ns++) {
            int nn = wn * 32 + ns * 8 + 2 * cc;
            *(float2*)(sg + m * SGST + nn)       = make_float2(acc[ms][ns][0], acc[ms][ns][1]);
            *(float2*)(sg + (m + 8) * SGST + nn) = make_float2(acc[ms][ns][2], acc[ms][ns][3]);
        }
    }
    __syncthreads();

    int r   = tid >> 2;
    int seg = tid & 3;
    int co  = mblk * 128 + r;
    float bias = (dir ? bb : bf)[co];
    float* og = g_xg + ((size_t)((dir * BB + n) * TT + t) * 256 + co) * NPIX + y0 * 32;
    const float* row = sg + r * SGST + seg * 64;
    #pragma unroll
    for (int i2 = 0; i2 < 16; i2++) {
        float4 v = *(const float4*)(row + i2 * 4);
        v.x += bias; v.y += bias; v.z += bias; v.w += bias;
        *(float4*)(og + seg * 64 + i2 * 4) = v;
    }
}

// ---------------------------------------------------------------------------
// Kernel 2: one recurrence step; B staged once with full 2-D halo,
// A triple-buffered in groups of 3 taps (1 barrier per group).
// grid 128 = nb(4) x mblk(2) x n(8) x dir(2); 512 threads.
// ---------------------------------------------------------------------------
__global__ void __launch_bounds__(512, 1)
lstm_step_mma(float* __restrict__ out, int t)
{
    extern __shared__ char smem[];
    uint32_t* smw = (uint32_t*)smem;
    uint32_t  sb  = smem_u32(smem);

    int tid = threadIdx.x, wid = tid >> 5, lane = tid & 31;
    int rr = lane >> 2, cc = lane & 3;
    int wm = wid & 1, wn = wid >> 1;

    int bid  = blockIdx.x;
    int nb   = bid & 3;
    int mblk = (bid >> 2) & 1;
    int n    = (bid >> 3) & 7;
    int dir  = (bid >> 6) & 1;
    int y0   = nb * 8;

    const float* hread  = g_h[t & 1]       + (size_t)(dir * BB + n) * HID * NPIX;
    float*       hwrite = g_h[(t & 1) ^ 1] + (size_t)(dir * BB + n) * HID * NPIX;
    float*       cbuf   = g_c              + (size_t)(dir * BB + n) * HID * NPIX;

    float acc[4][4][4];
    #pragma unroll
    for (int ms = 0; ms < 4; ms++)
        #pragma unroll
        for (int ns = 0; ns < 4; ns++)
            #pragma unroll
            for (int q = 0; q < 4; q++) acc[ms][ns][q] = 0.0f;

    auto cpA = [&](int g, int buf) {
        const float4* src = (const float4*)(g_wA +
            ((size_t)(dir * 2 + mblk) * 52 + g * 3) * 4096);
        uint32_t dstb = sb + (uint32_t)(SM_A_W + buf * TAPBUF_W) * 4;
        #pragma unroll
        for (int u = 0; u < 6; u++)
            cp16(dstb + (uint32_t)(u * 512 + tid) * 16, src + u * 512 + tid);
    };

    if (t > 0) {
        // ---- stage B once: 14 rows x 38 cols halo, 64 ci as 32 half2 ----
        for (int idx = tid; idx < B_W; idx += 512) {
            int q = idx / 532;
            int p = idx - q * 532;
            int r = p / 38, c = p - r * 38;
            int ys = y0 + r - 3, xs = c - 3;
            float lo = 0, hi = 0;
            if ((unsigned)ys < 32u && (unsigned)xs < 32u) {
                const float* hp = hread + (size_t)(2 * q) * NPIX + ys * 32 + xs;
                lo = hp[0]; hi = hp[NPIX];
            }
            int kc = q >> 3, qq = q & 7;
            int w = (kc >> 1) * B_KCP_W + p * 16 + (qq & 3) * 4 + (kc & 1) * 2 + (qq >> 2);
            smw[w] = packh2(lo, hi);
        }
        cpA(0, 0); cp_commit();
        cpA(1, 1); cp_commit();

        int bB = (wn * 38 + rr) * 16 + cc * 4;   // b-frag word base

        for (int g = 0; g < 17; g++) {
            if (g < 16) cp_wait1(); else cp_wait0();
            __syncthreads();
            if (g + 2 < 17) { cpA(g + 2, (g + 2) % 3); cp_commit(); }

            const uint32_t* As = smw + SM_A_W + (g % 3) * TAPBUF_W;
            int jmax = (g == 16) ? 1 : 3;
            #pragma unroll
            for (int jt = 0; jt < 3; jt++) {
                if (jt >= jmax) break;
                int j  = g * 3 + jt;
                int pw = bB + c_poff[j] * 16;
                #pragma unroll
                for (int kcp = 0; kcp < 2; kcp++) {
                    uint4 b4[4];
                    #pragma unroll
                    for (int ns = 0; ns < 4; ns++)
                        b4[ns] = *(const uint4*)(smw + kcp * B_KCP_W + pw + ns * 128);
                    #pragma unroll
                    for (int kh = 0; kh < 2; kh++) {
                        int kc = kcp * 2 + kh;
                        uint4 a4[4];
                        #pragma unroll
                        for (int ms = 0; ms < 4; ms++)
                            a4[ms] = *(const uint4*)(As + jt * 4096 +
                                      (kc * 8 + wm * 4 + ms) * 128 + lane * 4);
                        #pragma unroll
                        for (int ms = 0; ms < 4; ms++)
                            #pragma unroll
                            for (int ns = 0; ns < 4; ns++)
                                mma_f16(acc[ms][ns], (const uint32_t*)&a4[ms],
                                        (const uint32_t*)&b4[ns] + kh * 2);
                    }
                }
            }
        }
        __syncthreads();

        // ---- acc -> s_g gate staging ----
        float* sg = (float*)smem;
        #pragma unroll
        for (int ms = 0; ms < 4; ms++) {
            int m = wm * 64 + ms * 16 + rr;
            #pragma unroll
            for (int ns = 0; ns < 4; ns++) {
                int nn = wn * 32 + ns * 8 + 2 * cc;
                *(float2*)(sg + m * SGST + nn)       = make_float2(acc[ms][ns][0], acc[ms][ns][1]);
                *(float2*)(sg + (m + 8) * SGST + nn) = make_float2(acc[ms][ns][2], acc[ms][ns][3]);
            }
        }
        __syncthreads();
    }

    // ---- LSTM epilogue ----
    int tcur = dir ? (TT - 1 - t) : t;
    const float* xgp = g_xg + (size_t)(((dir * BB + n) * TT + tcur) * 256) * NPIX;
    const float* sg  = (const float*)smem;
    int hl  = tid >> 4;
    int px0 = (tid & 15) * 16;
    int hch = mblk * 32 + hl;

    #pragma unroll
    for (int p = 0; p < 16; p++) {
        int px = px0 + p;
        int yx = y0 * 32 + px;
        float hi = 0, hf = 0, hgg = 0, ho = 0;
        if (t > 0) {
            hi  = sg[(0 * 32 + hl) * SGST + px];
            hf  = sg[(1 * 32 + hl) * SGST + px];
            hgg = sg[(2 * 32 + hl) * SGST + px];
            ho  = sg[(3 * 32 + hl) * SGST + px];
        }
        float ig = hi  + xgp[(size_t)(0 * 64 + hch) * NPIX + yx];
        float fg = hf  + xgp[(size_t)(1 * 64 + hch) * NPIX + yx];
        float gg = hgg + xgp[(size_t)(2 * 64 + hch) * NPIX + yx];
        float og = ho  + xgp[(size_t)(3 * 64 + hch) * NPIX + yx];
        float cp = (t > 0) ? cbuf[(size_t)hch * NPIX + yx] : 0.0f;
        float cn = sigf(fg) * cp + sigf(ig) * tanh_fast(gg);
        float hn = sigf(og) * tanh_fast(cn);
        cbuf[(size_t)hch * NPIX + yx]   = cn;
        hwrite[(size_t)hch * NPIX + yx] = hn;
        out[(size_t)((n * TT + tcur) * (2 * HID) + dir * HID + hch) * NPIX + yx] = hn;
    }
}

// ---------------------------------------------------------------------------
extern "C" void kernel_launch(void* const* d_in, const int* in_sizes, int n_in,
                              void* d_out, int out_size)
{
    const float* x      = (const float*)d_in[0];
    const float* w_ih_f = (const float*)d_in[1];
    const float* w_hh_f = (const float*)d_in[2];
    const float* b_f    = (const float*)d_in[3];
    const float* w_ih_b = (const float*)d_in[4];
    const float* w_hh_b = (const float*)d_in[5];
    const float* b_b    = (const float*)d_in[6];
    float* out = (float*)d_out;

    cudaFuncSetAttribute(lstm_step_mma, cudaFuncAttributeMaxDynamicSharedMemorySize,
                         (int)SMEM_STEP);
    cudaFuncSetAttribute(input_conv_tc, cudaFuncAttributeMaxDynamicSharedMemorySize,
                         (int)SMEM_IC);

    prep_w_kernel<<<208, 256>>>(w_hh_f, w_hh_b);
    prep_wi_kernel<<<52, 256>>>(w_ih_f, w_ih_b);
    input_conv_tc<<<2048, 512, SMEM_IC>>>(x, b_f, b_b);
    for (int t = 0; t < TT; t++)
        lstm_step_mma<<<128, 512, SMEM_STEP>>>(out, t);
}

// round 7
// speedup vs baseline: 8.3272x; 1.3751x over previous
#include <cuda_runtime.h>
#include <cuda_fp16.h>
#include <cstdint>
#include <cstddef>

// ---------------- problem constants ----------------
constexpr int BB   = 8;
constexpr int TT   = 16;
constexpr int HID  = 64;
constexpr int NPIX = 1024;

// ---------------- step-kernel smem layout (uint32 words) ----------------
// Bh: [kcp(2)][pos(16) planes][580 px-stride] ; used px 0..569 (15 rows x 38 cols)
constexpr int BH_PLANE = 580;                 // %16 == 4 -> conflict-free b reads
constexpr int BH_KCP   = 16 * BH_PLANE;       // 9280
constexpr int BH_W     = 2 * BH_KCP;          // 18560
constexpr int BX_OFF   = BH_W;                // Bx: [570 px][2 words] (+pad)
constexpr int BX_W     = 1152;
constexpr int AR_OFF   = BX_OFF + BX_W;       // 19712
constexpr int GROUP_W  = 12 * 1024;           // 12 chunks of 1024 words
constexpr int AR_W     = 3 * GROUP_W;         // 36864
constexpr int SMEM_W   = AR_OFF + AR_W;       // 56576
constexpr size_t SMEM_STEP = (size_t)SMEM_W * 4;  // 226304 B
constexpr int SGST = 260;                     // epilogue gate staging stride (floats)

constexpr int NCH_FULL = 13 + 52 * 4;         // 221 chunks (13 input + 208 hidden)

// tap pixel offsets: poff[j] = (j/7)*38 + j%7
__device__ __constant__ int c_poff[52] = {
      0,  1,  2,  3,  4,  5,  6,
     38, 39, 40, 41, 42, 43, 44,
     76, 77, 78, 79, 80, 81, 82,
    114,115,116,117,118,119,120,
    152,153,154,155,156,157,158,
    190,191,192,193,194,195,196,
    228,229,230,231,232,233,234,
    266,267,268};

// ---------------- device scratch ----------------
__device__ uint32_t g_hp[2][(size_t)16 * 32 * NPIX];   // packed fp16 hidden (half2 ci-pairs)
__device__ float    g_c[(size_t)16 * HID * NPIX];      // cell state fp32
__device__ uint32_t g_wS[(size_t)4 * 240 * 1024];      // unified A chunk stream (padded)

// ---------------- helpers ----------------
__device__ __forceinline__ uint32_t smem_u32(const void* p) {
    uint32_t a;
    asm("{ .reg .u64 t; cvta.to.shared.u64 t, %1; cvt.u32.u64 %0, t; }" : "=r"(a) : "l"(p));
    return a;
}
__device__ __forceinline__ void mma_f16(float* c, const uint32_t* a, const uint32_t* b) {
    asm volatile(
        "mma.sync.aligned.m16n8k16.row.col.f32.f16.f16.f32 "
        "{%0,%1,%2,%3}, {%4,%5,%6,%7}, {%8,%9}, {%0,%1,%2,%3};"
        : "+f"(c[0]), "+f"(c[1]), "+f"(c[2]), "+f"(c[3])
        : "r"(a[0]), "r"(a[1]), "r"(a[2]), "r"(a[3]), "r"(b[0]), "r"(b[1]));
}
__device__ __forceinline__ void cp16(uint32_t dst, const void* src) {
    asm volatile("cp.async.cg.shared.global [%0], [%1], 16;" :: "r"(dst), "l"(src));
}
__device__ __forceinline__ void cp_commit() {
    asm volatile("cp.async.commit_group;" ::: "memory");
}
__device__ __forceinline__ void cp_wait0() {
    asm volatile("cp.async.wait_group 0;" ::: "memory");
}
__device__ __forceinline__ void cp_wait1() {
    asm volatile("cp.async.wait_group 1;" ::: "memory");
}
__device__ __forceinline__ uint32_t packh2(float lo, float hi) {
    __half2 h = __floats2half2_rn(lo, hi);
    return *(uint32_t*)&h;
}
__device__ __forceinline__ float sigf(float x) {
    return __fdividef(1.0f, 1.0f + __expf(-x));
}
__device__ __forceinline__ float tanh_fast(float x) {
    return __fdividef(2.0f, 1.0f + __expf(-2.0f * x)) - 1.0f;
}

// ---------------------------------------------------------------------------
// Kernel 0: build unified A chunk stream (fp16 mma fragment order).
// grid 884 = dm(4: dir*2+mblk) x chunk(221). Chunk word i = [mt8][lane32][reg4]:
//   m = mt*16 + (lane>>2) + (reg&1)*8 ;  k-pair = (lane&3) + (reg>>1)*4 (x2 +8 pattern)
//   co(m) = (m>>5)*64 + mblk*32 + (m&31)      (gate-major rows, PyTorch i,f,g,o)
// ---------------------------------------------------------------------------
__global__ void prep_w_kernel(const float* __restrict__ wihf, const float* __restrict__ whhf,
                              const float* __restrict__ wihb, const float* __restrict__ whhb)
{
    int bid  = blockIdx.x;
    int c    = bid % NCH_FULL;
    int dm   = bid / NCH_FULL;
    int mblk = dm & 1, dir = dm >> 1;
    const float* wih = dir ? wihb : wihf;
    const float* whh = dir ? whhb : whhf;
    uint32_t* dst = g_wS + ((size_t)dm * 240 + c) * 1024;

    for (int i = threadIdx.x; i < 1024; i += 256) {
        int reg  = i & 3;
        int lane = (i >> 2) & 31;
        int mt   = i >> 7;
        int m    = mt * 16 + (lane >> 2) + (reg & 1) * 8;
        int co   = (m >> 5) * 64 + mblk * 32 + (m & 31);
        float lo = 0.0f, hi = 0.0f;
        if (c < 13) {
            int pair = c * 8 + (lane & 3) + (reg >> 1) * 4;
            int j = pair >> 1, cip = pair & 1;
            if (j < 49) {
                int ky = j / 7, kx = j - ky * 7;
                int ci0 = cip * 2;
                lo = wih[((size_t)co * 3 + ci0) * 49 + ky * 7 + kx];
                if (ci0 + 1 < 3)
                    hi = wih[((size_t)co * 3 + ci0 + 1) * 49 + ky * 7 + kx];
            }
        } else {
            int hc = c - 13;
            int j = hc >> 2, kc = hc & 3;
            if (j < 49) {
                int ky = j / 7, kx = j - ky * 7;
                int k = kc * 16 + (lane & 3) * 2 + (reg >> 1) * 8;
                lo = whh[((size_t)co * HID + k)     * 49 + ky * 7 + kx];
                hi = whh[((size_t)co * HID + k + 1) * 49 + ky * 7 + kx];
            }
        }
        dst[i] = packh2(lo, hi);
    }
}

// ---------------------------------------------------------------------------
// Kernel 1: fully-fused recurrence step (input conv + hidden conv + LSTM).
// grid 128 = nb(4) x mblk(2) x n(8) x dir(2); 512 threads (16 warps).
// ---------------------------------------------------------------------------
__global__ void __launch_bounds__(512, 1)
lstm_step(const float* __restrict__ x,
          const float* __restrict__ bf, const float* __restrict__ bb,
          float* __restrict__ out, int t)
{
    extern __shared__ char smem[];
    uint32_t* smw = (uint32_t*)smem;
    uint32_t  sb  = smem_u32(smem);

    int tid = threadIdx.x, wid = tid >> 5, lane = tid & 31;
    int rr = lane >> 2, cc = lane & 3;
    int wm = wid & 1, wn = wid >> 1;

    int bid  = blockIdx.x;
    int nb   = bid & 3;
    int mblk = (bid >> 2) & 1;
    int n    = (bid >> 3) & 7;
    int dir  = (bid >> 6) & 1;
    int y0   = nb * 8;
    int dm   = dir * 2 + mblk;
    int dn   = dir * BB + n;
    int tcur = dir ? (TT - 1 - t) : t;

    const uint32_t* hpin  = g_hp[t & 1]       + (size_t)dn * 32 * NPIX;
    uint32_t*       hpout = g_hp[(t & 1) ^ 1] + (size_t)dn * 32 * NPIX;
    float*          cbuf  = g_c               + (size_t)dn * HID * NPIX;
    const float*    bias  = dir ? bb : bf;
    const float*    xin   = x + (size_t)(n * TT + tcur) * 3 * NPIX;

    float acc[4][4][4];
    #pragma unroll
    for (int ms = 0; ms < 4; ms++)
        #pragma unroll
        for (int ns = 0; ns < 4; ns++)
            #pragma unroll
            for (int q = 0; q < 4; q++) acc[ms][ns][q] = 0.0f;

    // ---- stage Bx: 15x38 halo of x, words = half2(ci0,ci1),(ci2,0) ----
    #pragma unroll
    for (int i = 0; i < 2; i++) {
        int px = tid + i * 512;
        if (px < 570) {
            int row = px / 38, col = px - row * 38;
            int y = y0 - 3 + row, xx = col - 3;
            float v0 = 0, v1 = 0, v2 = 0;
            if ((unsigned)y < 32u && (unsigned)xx < 32u) {
                int o = y * 32 + xx;
                v0 = xin[o]; v1 = xin[NPIX + o]; v2 = xin[2 * NPIX + o];
            }
            smw[BX_OFF + px * 2]     = packh2(v0, v1);
            smw[BX_OFF + px * 2 + 1] = packh2(v2, 0.0f);
        }
    }

    // ---- stage Bh from packed global h (t>0): 1 LDG.32 + 1 STS per word ----
    if (t > 0) {
        int q = tid >> 4, l = tid & 15;
        int kc = q >> 3, kh = kc & 1, qq = q & 7;
        int pos = kh * 8 + (qq & 3) * 2 + (qq >> 2);
        uint32_t sbase = (q >> 4) * BH_KCP + pos * BH_PLANE;
        const uint32_t* src = hpin + (size_t)q * NPIX;
        int row = 0, col = l;
        #pragma unroll 4
        for (int i = 0; i < 36; i++) {
            if (row < 15) {
                int px = row * 38 + col;
                int y = y0 - 3 + row, xx = col - 3;
                uint32_t w = 0;
                if ((unsigned)y < 32u && (unsigned)xx < 32u) w = src[y * 32 + xx];
                smw[sbase + px] = w;
            }
            col += 16;
            if (col >= 38) { col -= 38; row++; }
        }
    }

    // ---- A chunk-stream pipeline ----
    int nchunks = (t > 0) ? NCH_FULL : 13;
    int ngroups = (nchunks + 11) / 12;
    auto cpS = [&](int g, int buf) {
        const float4* src = (const float4*)(g_wS + ((size_t)dm * 240 + g * 12) * 1024);
        uint32_t dstb = sb + (uint32_t)(AR_OFF + buf * GROUP_W) * 4;
        #pragma unroll
        for (int u = 0; u < 6; u++)
            cp16(dstb + (uint32_t)(u * 512 + tid) * 16, src + u * 512 + tid);
    };
    int issued = 0;
    cpS(0, 0); cp_commit(); issued = 1;
    if (ngroups > 1) { cpS(1, 1); cp_commit(); issued = 2; }

    int pbh = wn * 38 + rr;             // pixel base (row wn, col rr)
    int bxb = BX_OFF + pbh * 2 + (cc & 1);

    for (int g = 0; g < ngroups; g++) {
        if (issued > g + 1) cp_wait1(); else cp_wait0();
        __syncthreads();
        if (issued < ngroups) { cpS(issued, issued % 3); cp_commit(); issued++; }

        const uint32_t* Ab = smw + AR_OFF + (g % 3) * GROUP_W + wm * 512 + lane * 4;
        int cbase = g * 12;
        int cnt = nchunks - cbase; if (cnt > 12) cnt = 12;

        for (int u = 0; u < cnt; u++) {
            int c = cbase + u;
            uint32_t b[4][2];
            if (c < 13) {
                int jb = c * 4 + (cc >> 1);
                int o1 = bxb + c_poff[jb] * 2;
                int o2 = bxb + c_poff[jb + 2] * 2;
                #pragma unroll
                for (int ns = 0; ns < 4; ns++) {
                    b[ns][0] = smw[o1 + ns * 16];
                    b[ns][1] = smw[o2 + ns * 16];
                }
            } else {
                int hc = c - 13;
                int j = hc >> 2, kc = hc & 3;
                int base = ((kc >> 1) * 16 + (kc & 1) * 8 + cc * 2) * BH_PLANE
                           + pbh + c_poff[j];
                #pragma unroll
                for (int ns = 0; ns < 4; ns++) {
                    b[ns][0] = smw[base + ns * 8];
                    b[ns][1] = smw[base + BH_PLANE + ns * 8];
                }
            }
            const uint32_t* Ac = Ab + u * 1024;
            uint4 a4[4];
            #pragma unroll
            for (int ms = 0; ms < 4; ms++)
                a4[ms] = *(const uint4*)(Ac + ms * 128);
            #pragma unroll
            for (int ms = 0; ms < 4; ms++)
                #pragma unroll
                for (int ns = 0; ns < 4; ns++)
                    mma_f16(acc[ms][ns], (const uint32_t*)&a4[ms], b[ns]);
        }
    }
    __syncthreads();

    // ---- acc -> s_g gate staging (aliases Bh/Bx/A-ring space) ----
    float* sg = (float*)smem;
    #pragma unroll
    for (int ms = 0; ms < 4; ms++) {
        int m = wm * 64 + ms * 16 + rr;
        #pragma unroll
        for (int ns = 0; ns < 4; ns++) {
            int nn = wn * 32 + ns * 8 + 2 * cc;
            *(float2*)(sg + m * SGST + nn)       = make_float2(acc[ms][ns][0], acc[ms][ns][1]);
            *(float2*)(sg + (m + 8) * SGST + nn) = make_float2(acc[ms][ns][2], acc[ms][ns][3]);
        }
    }
    __syncthreads();

    // ---- LSTM epilogue: thread = (hid pair, 8 px), all vector ops ----
    int hl2 = tid >> 5;                 // 0..15 pair index
    int px0 = (tid & 31) * 8;
    int qout = mblk * 16 + hl2;
    int yx0  = y0 * 32 + px0;

    float hn2[2][8];
    #pragma unroll
    for (int e = 0; e < 2; e++) {
        int hl  = 2 * hl2 + e;
        int ch  = mblk * 32 + hl;
        float bi = bias[0 * HID + ch];
        float bfg = bias[1 * HID + ch];
        float bg = bias[2 * HID + ch];
        float bo = bias[3 * HID + ch];
        const float* rI = sg + (0 * 32 + hl) * SGST + px0;
        const float* rF = sg + (1 * 32 + hl) * SGST + px0;
        const float* rG = sg + (2 * 32 + hl) * SGST + px0;
        const float* rO = sg + (3 * 32 + hl) * SGST + px0;
        float* cp_ptr = cbuf + (size_t)ch * NPIX + yx0;
        float* op     = out + ((size_t)((n * TT + tcur) * 2 * HID) + dir * HID + ch) * NPIX + yx0;
        #pragma unroll
        for (int v = 0; v < 2; v++) {
            float4 gI = *(const float4*)(rI + v * 4);
            float4 gF = *(const float4*)(rF + v * 4);
            float4 gG = *(const float4*)(rG + v * 4);
            float4 gO = *(const float4*)(rO + v * 4);
            float4 cv = make_float4(0, 0, 0, 0);
            if (t > 0) cv = *(const float4*)(cp_ptr + v * 4);
            float ig[4] = {gI.x + bi,  gI.y + bi,  gI.z + bi,  gI.w + bi};
            float fg[4] = {gF.x + bfg, gF.y + bfg, gF.z + bfg, gF.w + bfg};
            float gg[4] = {gG.x + bg,  gG.y + bg,  gG.z + bg,  gG.w + bg};
            float og[4] = {gO.x + bo,  gO.y + bo,  gO.z + bo,  gO.w + bo};
            float cold[4] = {cv.x, cv.y, cv.z, cv.w};
            float4 cnew, hnew;
            float* cn4 = (float*)&cnew;
            float* hn4 = (float*)&hnew;
            #pragma unroll
            for (int p = 0; p < 4; p++) {
                float cn = sigf(fg[p]) * cold[p] + sigf(ig[p]) * tanh_fast(gg[p]);
                float hn = sigf(og[p]) * tanh_fast(cn);
                cn4[p] = cn;
                hn4[p] = hn;
                hn2[e][v * 4 + p] = hn;
            }
            *(float4*)(cp_ptr + v * 4) = cnew;
            *(float4*)(op + v * 4)     = hnew;
        }
    }
    // packed fp16 h write (B-ready ci-pair words)
    uint32_t hw[8];
    #pragma unroll
    for (int p = 0; p < 8; p++) hw[p] = packh2(hn2[0][p], hn2[1][p]);
    uint32_t* hp = hpout + (size_t)qout * NPIX + yx0;
    *(uint4*)(hp)     = *(uint4*)(hw);
    *(uint4*)(hp + 4) = *(uint4*)(hw + 4);
}

// ---------------------------------------------------------------------------
extern "C" void kernel_launch(void* const* d_in, const int* in_sizes, int n_in,
                              void* d_out, int out_size)
{
    const float* x      = (const float*)d_in[0];
    const float* w_ih_f = (const float*)d_in[1];
    const float* w_hh_f = (const float*)d_in[2];
    const float* b_f    = (const float*)d_in[3];
    const float* w_ih_b = (const float*)d_in[4];
    const float* w_hh_b = (const float*)d_in[5];
    const float* b_b    = (const float*)d_in[6];
    float* out = (float*)d_out;

    cudaFuncSetAttribute(lstm_step, cudaFuncAttributeMaxDynamicSharedMemorySize,
                         (int)SMEM_STEP);

    prep_w_kernel<<<4 * NCH_FULL, 256>>>(w_ih_f, w_hh_f, w_ih_b, w_hh_b);
    for (int t = 0; t < TT; t++)
        lstm_step<<<128, 512, SMEM_STEP>>>(x, b_f, b_b, out, t);
}

// round 8
// speedup vs baseline: 8.5918x; 1.0318x over previous
#include <cuda_runtime.h>
#include <cuda_fp16.h>
#include <cstdint>
#include <cstddef>

// ---------------- problem constants ----------------
constexpr int BB   = 8;
constexpr int TT   = 16;
constexpr int HID  = 64;
constexpr int NPIX = 1024;

// ---------------- step-kernel smem layout (uint32 words) ----------------
// Bh paired layout: gidx(16 = kc*4+cc) planes of stride 776 words;
//   word = gidx*776 + hx*2 + half   (hx = halo pixel 0..379, 10 rows x 38 cols)
constexpr int BH_GSTR = 776;
constexpr int BH_W    = 16 * BH_GSTR;          // 12416
constexpr int BX_OFF  = BH_W;                  // Bx: [400 px][2 words] (380 real + zero pad)
constexpr int BX_W    = 800;
constexpr int AR_OFF  = BX_OFF + BX_W;         // 13216
constexpr int GROUP_W = 4 * 1024;              // 4 chunks per group
constexpr int AR_W    = 3 * GROUP_W;           // 12288
constexpr int SMEM_W  = AR_OFF + AR_W;         // 25504
constexpr size_t SMEM_STEP = (size_t)SMEM_W * 4;   // 102016 B  (x2 CTAs <= 228KB)
constexpr int SGST = 132;                      // epilogue gate staging stride (floats)

constexpr int NCH = 13 + 49 * 4;               // 209 real chunks (no zero-pad taps)

// tap pixel offsets: poff[j] = (j/7)*38 + j%7
__device__ __constant__ int c_poff[52] = {
      0,  1,  2,  3,  4,  5,  6,
     38, 39, 40, 41, 42, 43, 44,
     76, 77, 78, 79, 80, 81, 82,
    114,115,116,117,118,119,120,
    152,153,154,155,156,157,158,
    190,191,192,193,194,195,196,
    228,229,230,231,232,233,234,
    266,267,268};

// ---------------- device scratch ----------------
__device__ uint32_t g_hp[2][(size_t)16 * 32 * NPIX];   // packed fp16 hidden (half2 ci-pairs)
__device__ float    g_c[(size_t)16 * HID * NPIX];      // cell state fp32
__device__ uint32_t g_wS[(size_t)4 * 240 * 1024];      // unified A chunk stream (padded)

// ---------------- helpers ----------------
__device__ __forceinline__ uint32_t smem_u32(const void* p) {
    uint32_t a;
    asm("{ .reg .u64 t; cvta.to.shared.u64 t, %1; cvt.u32.u64 %0, t; }" : "=r"(a) : "l"(p));
    return a;
}
__device__ __forceinline__ void mma_f16(float* c, const uint32_t* a, const uint32_t* b) {
    asm volatile(
        "mma.sync.aligned.m16n8k16.row.col.f32.f16.f16.f32 "
        "{%0,%1,%2,%3}, {%4,%5,%6,%7}, {%8,%9}, {%0,%1,%2,%3};"
        : "+f"(c[0]), "+f"(c[1]), "+f"(c[2]), "+f"(c[3])
        : "r"(a[0]), "r"(a[1]), "r"(a[2]), "r"(a[3]), "r"(b[0]), "r"(b[1]));
}
__device__ __forceinline__ void cp16(uint32_t dst, const void* src) {
    asm volatile("cp.async.cg.shared.global [%0], [%1], 16;" :: "r"(dst), "l"(src));
}
__device__ __forceinline__ void cp_commit() {
    asm volatile("cp.async.commit_group;" ::: "memory");
}
__device__ __forceinline__ void cp_wait0() {
    asm volatile("cp.async.wait_group 0;" ::: "memory");
}
__device__ __forceinline__ void cp_wait1() {
    asm volatile("cp.async.wait_group 1;" ::: "memory");
}
__device__ __forceinline__ uint32_t packh2(float lo, float hi) {
    __half2 h = __floats2half2_rn(lo, hi);
    return *(uint32_t*)&h;
}
__device__ __forceinline__ float sigf(float x) {
    return __fdividef(1.0f, 1.0f + __expf(-x));
}
__device__ __forceinline__ float tanh_fast(float x) {
    return __fdividef(2.0f, 1.0f + __expf(-2.0f * x)) - 1.0f;
}

// ---------------------------------------------------------------------------
// Kernel 0: build unified A chunk stream (fp16 mma fragment order).
// grid 884 = dm(4) x chunk(221 slots; only 209 used at runtime).
// ---------------------------------------------------------------------------
__global__ void prep_w_kernel(const float* __restrict__ wihf, const float* __restrict__ whhf,
                              const float* __restrict__ wihb, const float* __restrict__ whhb)
{
    int bid  = blockIdx.x;
    int c    = bid % 221;
    int dm   = bid / 221;
    int mblk = dm & 1, dir = dm >> 1;
    const float* wih = dir ? wihb : wihf;
    const float* whh = dir ? whhb : whhf;
    uint32_t* dst = g_wS + ((size_t)dm * 240 + c) * 1024;

    for (int i = threadIdx.x; i < 1024; i += 256) {
        int reg  = i & 3;
        int lane = (i >> 2) & 31;
        int mt   = i >> 7;
        int m    = mt * 16 + (lane >> 2) + (reg & 1) * 8;
        int co   = (m >> 5) * 64 + mblk * 32 + (m & 31);
        float lo = 0.0f, hi = 0.0f;
        if (c < 13) {
            int pair = c * 8 + (lane & 3) + (reg >> 1) * 4;
            int j = pair >> 1, cip = pair & 1;
            if (j < 49) {
                int ky = j / 7, kx = j - ky * 7;
                int ci0 = cip * 2;
                lo = wih[((size_t)co * 3 + ci0) * 49 + ky * 7 + kx];
                if (ci0 + 1 < 3)
                    hi = wih[((size_t)co * 3 + ci0 + 1) * 49 + ky * 7 + kx];
            }
        } else {
            int hc = c - 13;
            int j = hc >> 2, kc = hc & 3;
            if (j < 49) {
                int ky = j / 7, kx = j - ky * 7;
                int k = kc * 16 + (lane & 3) * 2 + (reg >> 1) * 8;
                lo = whh[((size_t)co * HID + k)     * 49 + ky * 7 + kx];
                hi = whh[((size_t)co * HID + k + 1) * 49 + ky * 7 + kx];
            }
        }
        dst[i] = packh2(lo, hi);
    }
}

// ---------------------------------------------------------------------------
// Kernel 1: fully-fused recurrence step (input conv + hidden conv + LSTM).
// grid 256 = rb(8) x mblk(2) x n(8) x dir(2); 256 threads (8 warps); 2 CTAs/SM.
// CTA tile: M=128 (4 gates x 32 hid), N=128 px (4 rows).
// ---------------------------------------------------------------------------
__global__ void __launch_bounds__(256, 2)
lstm_step(const float* __restrict__ x,
          const float* __restrict__ bf, const float* __restrict__ bb,
          float* __restrict__ out, int t)
{
    extern __shared__ char smem[];
    uint32_t* smw = (uint32_t*)smem;
    uint32_t  sb  = smem_u32(smem);

    int tid = threadIdx.x, wid = tid >> 5, lane = tid & 31;
    int rr = lane >> 2, cc = lane & 3;
    int wm = wid & 1, wn = wid >> 1;          // wn = output row 0..3

    int bid  = blockIdx.x;
    int rb   = bid & 7;
    int mblk = (bid >> 3) & 1;
    int n    = (bid >> 4) & 7;
    int dir  = (bid >> 7) & 1;
    int y0   = rb * 4;
    int dm   = dir * 2 + mblk;
    int dn   = dir * BB + n;
    int tcur = dir ? (TT - 1 - t) : t;

    const uint32_t* hpin  = g_hp[t & 1]       + (size_t)dn * 32 * NPIX;
    uint32_t*       hpout = g_hp[(t & 1) ^ 1] + (size_t)dn * 32 * NPIX;
    float*          cbuf  = g_c               + (size_t)dn * HID * NPIX;
    const float*    bias  = dir ? bb : bf;
    const float*    xin   = x + (size_t)(n * TT + tcur) * 3 * NPIX;

    float acc[4][4][4];
    #pragma unroll
    for (int ms = 0; ms < 4; ms++)
        #pragma unroll
        for (int ns = 0; ns < 4; ns++)
            #pragma unroll
            for (int q = 0; q < 4; q++) acc[ms][ns][q] = 0.0f;

    // ---- stage Bx: 10x38 halo of x (+zero pad to px 400) ----
    #pragma unroll
    for (int i = 0; i < 2; i++) {
        int px = tid + i * 256;
        if (px < 400) {
            float v0 = 0, v1 = 0, v2 = 0;
            if (px < 380) {
                int row = px / 38, col = px - row * 38;
                int y = y0 - 3 + row, xx = col - 3;
                if ((unsigned)y < 32u && (unsigned)xx < 32u) {
                    int o = y * 32 + xx;
                    v0 = xin[o]; v1 = xin[NPIX + o]; v2 = xin[2 * NPIX + o];
                }
            }
            smw[BX_OFF + px * 2]     = packh2(v0, v1);
            smw[BX_OFF + px * 2 + 1] = packh2(v2, 0.0f);
        }
    }

    // ---- stage Bh paired (t>0): thread = (gidx, t16); STS.64 per px ----
    if (t > 0) {
        int gidx = tid >> 4, t16 = tid & 15;
        int q0 = ((gidx >> 2) << 3) + (gidx & 3);
        const uint32_t* s0 = hpin + (size_t)q0 * NPIX;
        const uint32_t* s1 = hpin + (size_t)(q0 + 4) * NPIX;
        uint32_t* dstp = smw + gidx * BH_GSTR;
        #pragma unroll 4
        for (int i = 0; i < 24; i++) {
            int hx = t16 + i * 16;
            if (hx < 380) {
                int row = hx / 38, col = hx - row * 38;
                int y = y0 - 3 + row, xx = col - 3;
                uint32_t w0 = 0, w1 = 0;
                if ((unsigned)y < 32u && (unsigned)xx < 32u) {
                    int o = y * 32 + xx;
                    w0 = s0[o]; w1 = s1[o];
                }
                *(uint2*)(dstp + hx * 2) = make_uint2(w0, w1);
            }
        }
    }

    // ---- A chunk-stream pipeline: groups of 4 chunks, 3 smem buffers ----
    int nchunks = (t > 0) ? NCH : 13;
    int ngroups = (nchunks + 3) / 4;
    auto cpS = [&](int g, int buf) {
        const float4* src = (const float4*)(g_wS + ((size_t)dm * 240 + g * 4) * 1024);
        uint32_t dstb = sb + (uint32_t)(AR_OFF + buf * GROUP_W) * 4;
        #pragma unroll
        for (int u = 0; u < 4; u++)
            cp16(dstb + (uint32_t)(u * 256 + tid) * 16, src + u * 256 + tid);
    };
    int issued = 0;
    cpS(0, 0); cp_commit(); issued = 1;
    if (ngroups > 1) { cpS(1, 1); cp_commit(); issued = 2; }

    int pbh = wn * 38 + rr;               // halo pixel base (row wn, col rr)
    int bxb = BX_OFF + pbh * 2 + (cc & 1);

    for (int g = 0; g < ngroups; g++) {
        if (issued > g + 1) cp_wait1(); else cp_wait0();
        __syncthreads();
        if (issued < ngroups) { cpS(issued, issued % 3); cp_commit(); issued++; }

        const uint32_t* Ab = smw + AR_OFF + (g % 3) * GROUP_W + wm * 512 + lane * 4;
        int cbase = g * 4;
        int cnt = nchunks - cbase; if (cnt > 4) cnt = 4;

        for (int u = 0; u < cnt; u++) {
            int c = cbase + u;
            uint32_t b[4][2];
            if (c < 13) {
                int jb = c * 4 + (cc >> 1);
                int o1 = bxb + c_poff[jb] * 2;
                int o2 = bxb + c_poff[jb + 2] * 2;
                #pragma unroll
                for (int ns = 0; ns < 4; ns++) {
                    b[ns][0] = smw[o1 + ns * 16];
                    b[ns][1] = smw[o2 + ns * 16];
                }
            } else {
                int hc = c - 13;
                int j = hc >> 2, kc = hc & 3;
                int base = (kc * 4 + cc) * BH_GSTR + (pbh + c_poff[j]) * 2;
                #pragma unroll
                for (int ns = 0; ns < 4; ns++)
                    *(uint2*)b[ns] = *(const uint2*)(smw + base + ns * 16);
            }
            const uint32_t* Ac = Ab + u * 1024;
            uint4 a4[4];
            #pragma unroll
            for (int ms = 0; ms < 4; ms++)
                a4[ms] = *(const uint4*)(Ac + ms * 128);
            #pragma unroll
            for (int ms = 0; ms < 4; ms++)
                #pragma unroll
                for (int ns = 0; ns < 4; ns++)
                    mma_f16(acc[ms][ns], (const uint32_t*)&a4[ms], b[ns]);
        }
    }
    __syncthreads();

    // ---- acc -> s_g gate staging (aliases Bh/Bx/A-ring space) ----
    float* sg = (float*)smem;
    #pragma unroll
    for (int ms = 0; ms < 4; ms++) {
        int m = wm * 64 + ms * 16 + rr;
        #pragma unroll
        for (int ns = 0; ns < 4; ns++) {
            int nn = wn * 32 + ns * 8 + 2 * cc;
            *(float2*)(sg + m * SGST + nn)       = make_float2(acc[ms][ns][0], acc[ms][ns][1]);
            *(float2*)(sg + (m + 8) * SGST + nn) = make_float2(acc[ms][ns][2], acc[ms][ns][3]);
        }
    }
    __syncthreads();

    // ---- LSTM epilogue: thread = (hid pair, 8 px), all vector ops ----
    int hl2 = tid >> 4;                   // 0..15 pair index
    int px0 = (tid & 15) * 8;             // 0..120
    int qout = mblk * 16 + hl2;
    int yx0  = y0 * 32 + px0;

    float hn2[2][8];
    #pragma unroll
    for (int e = 0; e < 2; e++) {
        int hl  = 2 * hl2 + e;
        int ch  = mblk * 32 + hl;
        float bi  = bias[0 * HID + ch];
        float bfg = bias[1 * HID + ch];
        float bg  = bias[2 * HID + ch];
        float bo  = bias[3 * HID + ch];
        const float* rI = sg + (0 * 32 + hl) * SGST + px0;
        const float* rF = sg + (1 * 32 + hl) * SGST + px0;
        const float* rG = sg + (2 * 32 + hl) * SGST + px0;
        const float* rO = sg + (3 * 32 + hl) * SGST + px0;
        float* cp_ptr = cbuf + (size_t)ch * NPIX + yx0;
        float* op     = out + ((size_t)((n * TT + tcur) * 2 * HID) + dir * HID + ch) * NPIX + yx0;
        #pragma unroll
        for (int v = 0; v < 2; v++) {
            float4 gI = *(const float4*)(rI + v * 4);
            float4 gF = *(const float4*)(rF + v * 4);
            float4 gG = *(const float4*)(rG + v * 4);
            float4 gO = *(const float4*)(rO + v * 4);
            float4 cv = make_float4(0, 0, 0, 0);
            if (t > 0) cv = *(const float4*)(cp_ptr + v * 4);
            float ig[4] = {gI.x + bi,  gI.y + bi,  gI.z + bi,  gI.w + bi};
            float fg[4] = {gF.x + bfg, gF.y + bfg, gF.z + bfg, gF.w + bfg};
            float gg[4] = {gG.x + bg,  gG.y + bg,  gG.z + bg,  gG.w + bg};
            float og[4] = {gO.x + bo,  gO.y + bo,  gO.z + bo,  gO.w + bo};
            float cold[4] = {cv.x, cv.y, cv.z, cv.w};
            float4 cnew, hnew;
            float* cn4 = (float*)&cnew;
            float* hn4 = (float*)&hnew;
            #pragma unroll
            for (int p = 0; p < 4; p++) {
                float cn = sigf(fg[p]) * cold[p] + sigf(ig[p]) * tanh_fast(gg[p]);
                float hn = sigf(og[p]) * tanh_fast(cn);
                cn4[p] = cn;
                hn4[p] = hn;
                hn2[e][v * 4 + p] = hn;
            }
            *(float4*)(cp_ptr + v * 4) = cnew;
            *(float4*)(op + v * 4)     = hnew;
        }
    }
    // packed fp16 h write (B-ready ci-pair words)
    uint32_t hw[8];
    #pragma unroll
    for (int p = 0; p < 8; p++) hw[p] = packh2(hn2[0][p], hn2[1][p]);
    uint32_t* hp = hpout + (size_t)qout * NPIX + yx0;
    *(uint4*)(hp)     = *(uint4*)(hw);
    *(uint4*)(hp + 4) = *(uint4*)(hw + 4);
}

// ---------------------------------------------------------------------------
extern "C" void kernel_launch(void* const* d_in, const int* in_sizes, int n_in,
                              void* d_out, int out_size)
{
    const float* x      = (const float*)d_in[0];
    const float* w_ih_f = (const float*)d_in[1];
    const float* w_hh_f = (const float*)d_in[2];
    const float* b_f    = (const float*)d_in[3];
    const float* w_ih_b = (const float*)d_in[4];
    const float* w_hh_b = (const float*)d_in[5];
    const float* b_b    = (const float*)d_in[6];
    float* out = (float*)d_out;

    cudaFuncSetAttribute(lstm_step, cudaFuncAttributeMaxDynamicSharedMemorySize,
                         (int)SMEM_STEP);

    prep_w_kernel<<<884, 256>>>(w_ih_f, w_hh_f, w_ih_b, w_hh_b);
    for (int t = 0; t < TT; t++)
        lstm_step<<<256, 256, SMEM_STEP>>>(x, b_f, b_b, out, t);
}

// round 9
// speedup vs baseline: 8.6744x; 1.0096x over previous
#include <cuda_runtime.h>
#include <cuda_fp16.h>
#include <cstdint>
#include <cstddef>

// ---------------- problem constants ----------------
constexpr int BB   = 8;
constexpr int TT   = 16;
constexpr int HID  = 64;
constexpr int NPIX = 1024;

// ---------------- step-kernel smem layout (uint32 words) ----------------
// Bh: word = hx*36 + cc*8 + kc*2 + h   (hx = halo px 0..379, 10 rows x 38 cols)
constexpr int BH_PXSTR = 36;                  // 4 cc * 8 + 4 pad -> conflict-free LDS.128
constexpr int BH_W     = 380 * BH_PXSTR;      // 13680
constexpr int BX_OFF   = BH_W;                // Bx: [400 px][2 words] (380 real + pad)
constexpr int BX_W     = 800;
constexpr int AR_OFF   = BX_OFF + BX_W;       // 14480
constexpr int GROUP_W  = 4 * 1024;            // 4 chunks per group (one tap j)
constexpr int AR_W     = 3 * GROUP_W;         // 12288
constexpr int SMEM_W   = AR_OFF + AR_W;       // 26768
constexpr size_t SMEM_STEP = (size_t)SMEM_W * 4;   // 107072 B (x2 CTAs <= 228KB)
constexpr int SGST = 132;                     // epilogue gate staging stride (floats)

// chunk stream: 0..195 hidden (j*4+kc), 196..208 input, 209..211 zero pad
constexpr int NG_FULL = 53;                   // 49 hidden groups + 4 input groups
constexpr int G_IN0   = 49;

// tap pixel offsets: poff[j] = (j/7)*38 + j%7
__device__ __constant__ int c_poff[52] = {
      0,  1,  2,  3,  4,  5,  6,
     38, 39, 40, 41, 42, 43, 44,
     76, 77, 78, 79, 80, 81, 82,
    114,115,116,117,118,119,120,
    152,153,154,155,156,157,158,
    190,191,192,193,194,195,196,
    228,229,230,231,232,233,234,
    266,267,268};

// ---------------- device scratch ----------------
__device__ uint32_t g_hp[2][(size_t)16 * 32 * NPIX];   // packed fp16 hidden (half2 ci-pairs)
__device__ float    g_c[(size_t)16 * HID * NPIX];      // cell state fp32
__device__ uint32_t g_wS[(size_t)4 * 240 * 1024];      // unified A chunk stream

// ---------------- helpers ----------------
__device__ __forceinline__ uint32_t smem_u32(const void* p) {
    uint32_t a;
    asm("{ .reg .u64 t; cvta.to.shared.u64 t, %1; cvt.u32.u64 %0, t; }" : "=r"(a) : "l"(p));
    return a;
}
__device__ __forceinline__ void mma_f16(float* c, const uint32_t* a,
                                        uint32_t b0, uint32_t b1) {
    asm volatile(
        "mma.sync.aligned.m16n8k16.row.col.f32.f16.f16.f32 "
        "{%0,%1,%2,%3}, {%4,%5,%6,%7}, {%8,%9}, {%0,%1,%2,%3};"
        : "+f"(c[0]), "+f"(c[1]), "+f"(c[2]), "+f"(c[3])
        : "r"(a[0]), "r"(a[1]), "r"(a[2]), "r"(a[3]), "r"(b0), "r"(b1));
}
__device__ __forceinline__ void cp16(uint32_t dst, const void* src) {
    asm volatile("cp.async.cg.shared.global [%0], [%1], 16;" :: "r"(dst), "l"(src));
}
__device__ __forceinline__ void cp_commit() {
    asm volatile("cp.async.commit_group;" ::: "memory");
}
__device__ __forceinline__ void cp_wait0() {
    asm volatile("cp.async.wait_group 0;" ::: "memory");
}
__device__ __forceinline__ void cp_wait1() {
    asm volatile("cp.async.wait_group 1;" ::: "memory");
}
__device__ __forceinline__ uint32_t packh2(float lo, float hi) {
    __half2 h = __floats2half2_rn(lo, hi);
    return *(uint32_t*)&h;
}
__device__ __forceinline__ float sigf(float x) {
    return __fdividef(1.0f, 1.0f + __expf(-x));
}
__device__ __forceinline__ float tanh_fast(float x) {
    return __fdividef(2.0f, 1.0f + __expf(-2.0f * x)) - 1.0f;
}

// ---------------------------------------------------------------------------
// Kernel 0: build unified A chunk stream. grid 848 = dm(4) x chunk(212).
// ---------------------------------------------------------------------------
__global__ void prep_w_kernel(const float* __restrict__ wihf, const float* __restrict__ whhf,
                              const float* __restrict__ wihb, const float* __restrict__ whhb)
{
    int bid  = blockIdx.x;
    int c    = bid % 212;
    int dm   = bid / 212;
    int mblk = dm & 1, dir = dm >> 1;
    const float* wih = dir ? wihb : wihf;
    const float* whh = dir ? whhb : whhf;
    uint32_t* dst = g_wS + ((size_t)dm * 240 + c) * 1024;

    for (int i = threadIdx.x; i < 1024; i += 256) {
        int reg  = i & 3;
        int lane = (i >> 2) & 31;
        int mt   = i >> 7;
        int m    = mt * 16 + (lane >> 2) + (reg & 1) * 8;
        int co   = (m >> 5) * 64 + mblk * 32 + (m & 31);
        float lo = 0.0f, hi = 0.0f;
        if (c < 196) {                    // hidden: j = c>>2, kc = c&3
            int j = c >> 2, kc = c & 3;
            int ky = j / 7, kx = j - ky * 7;
            int k = kc * 16 + (lane & 3) * 2 + (reg >> 1) * 8;
            lo = whh[((size_t)co * HID + k)     * 49 + ky * 7 + kx];
            hi = whh[((size_t)co * HID + k + 1) * 49 + ky * 7 + kx];
        } else if (c < 209) {             // input
            int ic = c - 196;
            int pair = ic * 8 + (lane & 3) + (reg >> 1) * 4;
            int j = pair >> 1, cip = pair & 1;
            if (j < 49) {
                int ky = j / 7, kx = j - ky * 7;
                int ci0 = cip * 2;
                lo = wih[((size_t)co * 3 + ci0) * 49 + ky * 7 + kx];
                if (ci0 + 1 < 3)
                    hi = wih[((size_t)co * 3 + ci0 + 1) * 49 + ky * 7 + kx];
            }
        }
        dst[i] = packh2(lo, hi);
    }
}

// ---------------------------------------------------------------------------
// Kernel 1: fully-fused recurrence step.
// grid 256 = rb(8) x mblk(2) x n(8) x dir(2); 256 threads; 2 CTAs/SM.
// ---------------------------------------------------------------------------
__global__ void __launch_bounds__(256, 2)
lstm_step(const float* __restrict__ x,
          const float* __restrict__ bf, const float* __restrict__ bb,
          float* __restrict__ out, int t)
{
    extern __shared__ char smem[];
    uint32_t* smw = (uint32_t*)smem;
    uint32_t  sb  = smem_u32(smem);

    int tid = threadIdx.x, wid = tid >> 5, lane = tid & 31;
    int rr = lane >> 2, cc = lane & 3;
    int wm = wid & 1, wn = wid >> 1;          // wn = output row 0..3

    int bid  = blockIdx.x;
    int rb   = bid & 7;
    int mblk = (bid >> 3) & 1;
    int n    = (bid >> 4) & 7;
    int dir  = (bid >> 7) & 1;
    int y0   = rb * 4;
    int dm   = dir * 2 + mblk;
    int dn   = dir * BB + n;
    int tcur = dir ? (TT - 1 - t) : t;

    const uint32_t* hpin  = g_hp[t & 1]       + (size_t)dn * 32 * NPIX;
    uint32_t*       hpout = g_hp[(t & 1) ^ 1] + (size_t)dn * 32 * NPIX;
    float*          cbuf  = g_c               + (size_t)dn * HID * NPIX;
    const float*    bias  = dir ? bb : bf;
    const float*    xin   = x + (size_t)(n * TT + tcur) * 3 * NPIX;

    // ---- prefetch first two A groups BEFORE staging (hide L2 latency) ----
    int nG = (t > 0) ? NG_FULL : 4;
    int g0 = (t > 0) ? 0 : G_IN0;
    auto cpS = [&](int g, int buf) {
        const float4* src = (const float4*)(g_wS + ((size_t)dm * 240 + g * 4) * 1024);
        uint32_t dstb = sb + (uint32_t)(AR_OFF + buf * GROUP_W) * 4;
        #pragma unroll
        for (int u = 0; u < 4; u++)
            cp16(dstb + (uint32_t)(u * 256 + tid) * 16, src + u * 256 + tid);
    };
    cpS(g0, 0);     cp_commit();
    cpS(g0 + 1, 1); cp_commit();
    int issued = 2;

    float acc[4][4][4];
    #pragma unroll
    for (int ms = 0; ms < 4; ms++)
        #pragma unroll
        for (int ns = 0; ns < 4; ns++)
            #pragma unroll
            for (int q = 0; q < 4; q++) acc[ms][ns][q] = 0.0f;

    // ---- stage Bx: 10x38 halo of x (+zero pad to px 400) ----
    #pragma unroll
    for (int i = 0; i < 2; i++) {
        int px = tid + i * 256;
        if (px < 400) {
            float v0 = 0, v1 = 0, v2 = 0;
            if (px < 380) {
                int row = px / 38, col = px - row * 38;
                int y = y0 - 3 + row, xx = col - 3;
                if ((unsigned)y < 32u && (unsigned)xx < 32u) {
                    int o = y * 32 + xx;
                    v0 = xin[o]; v1 = xin[NPIX + o]; v2 = xin[2 * NPIX + o];
                }
            }
            smw[BX_OFF + px * 2]     = packh2(v0, v1);
            smw[BX_OFF + px * 2 + 1] = packh2(v2, 0.0f);
        }
    }

    // ---- stage Bh (t>0): thread = (q 0..15, t16); planes q and q+16 ----
    if (t > 0) {
        int q = tid >> 4, t16 = tid & 15;
        // off(q) = cc*8 + kc*2 + h ;  q = kc*8 + cc + 4h
        int offa = (q & 3) * 8 + (q >> 3) * 2 + ((q >> 2) & 1);
        const uint32_t* s0 = hpin + (size_t)q * NPIX;
        const uint32_t* s1 = hpin + (size_t)(q + 16) * NPIX;
        #pragma unroll 4
        for (int i = 0; i < 24; i++) {
            int hx = t16 + i * 16;
            if (hx < 380) {
                int row = hx / 38, col = hx - row * 38;
                int y = y0 - 3 + row, xx = col - 3;
                uint32_t w0 = 0, w1 = 0;
                if ((unsigned)y < 32u && (unsigned)xx < 32u) {
                    int o = y * 32 + xx;
                    w0 = s0[o]; w1 = s1[o];
                }
                smw[hx * BH_PXSTR + offa]     = w0;   // kc
                smw[hx * BH_PXSTR + offa + 4] = w1;   // kc+2
            }
        }
    }

    int pbh = wn * 38 + rr;               // halo pixel base
    int bxb = BX_OFF + pbh * 2 + (cc & 1);

    for (int gi = 0; gi < nG; gi++) {
        int g = g0 + gi;
        if (issued > gi + 1) cp_wait1(); else cp_wait0();
        __syncthreads();
        if (issued < nG) { cpS(g0 + issued, issued % 3); cp_commit(); issued++; }

        const uint32_t* Ab = smw + AR_OFF + (gi % 3) * GROUP_W + wm * 512 + lane * 4;

        if (g < G_IN0) {
            // ---- hidden group: one tap j = g, 4 kc chunks ----
            int base = (pbh + c_poff[g]) * BH_PXSTR + cc * 8;
            uint4 b0[4], b1[4];
            #pragma unroll
            for (int ns = 0; ns < 4; ns++) {
                b0[ns] = *(const uint4*)(smw + base + ns * (8 * BH_PXSTR));
                b1[ns] = *(const uint4*)(smw + base + ns * (8 * BH_PXSTR) + 4);
            }
            #pragma unroll
            for (int kc = 0; kc < 4; kc++) {
                #pragma unroll
                for (int ms = 0; ms < 4; ms++) {
                    uint4 a4 = *(const uint4*)(Ab + kc * 1024 + ms * 128);
                    #pragma unroll
                    for (int ns = 0; ns < 4; ns++) {
                        uint32_t w0, w1;
                        if (kc == 0)      { w0 = b0[ns].x; w1 = b0[ns].y; }
                        else if (kc == 1) { w0 = b0[ns].z; w1 = b0[ns].w; }
                        else if (kc == 2) { w0 = b1[ns].x; w1 = b1[ns].y; }
                        else              { w0 = b1[ns].z; w1 = b1[ns].w; }
                        mma_f16(acc[ms][ns], (const uint32_t*)&a4, w0, w1);
                    }
                }
            }
        } else {
            // ---- input group: chunks ic = (g-49)*4+u, cnt real ----
            int icb = (g - G_IN0) * 4;
            int cnt = 13 - icb; if (cnt > 4) cnt = 4;
            for (int u = 0; u < cnt; u++) {
                int ic = icb + u;
                int jb = ic * 4 + (cc >> 1);
                int o1 = bxb + c_poff[jb] * 2;
                int o2 = bxb + c_poff[jb + 2] * 2;
                uint32_t b[4][2];
                #pragma unroll
                for (int ns = 0; ns < 4; ns++) {
                    b[ns][0] = smw[o1 + ns * 16];
                    b[ns][1] = smw[o2 + ns * 16];
                }
                #pragma unroll
                for (int ms = 0; ms < 4; ms++) {
                    uint4 a4 = *(const uint4*)(Ab + u * 1024 + ms * 128);
                    #pragma unroll
                    for (int ns = 0; ns < 4; ns++)
                        mma_f16(acc[ms][ns], (const uint32_t*)&a4, b[ns][0], b[ns][1]);
                }
            }
        }
    }
    __syncthreads();

    // ---- acc -> s_g gate staging ----
    float* sg = (float*)smem;
    #pragma unroll
    for (int ms = 0; ms < 4; ms++) {
        int m = wm * 64 + ms * 16 + rr;
        #pragma unroll
        for (int ns = 0; ns < 4; ns++) {
            int nn = wn * 32 + ns * 8 + 2 * cc;
            *(float2*)(sg + m * SGST + nn)       = make_float2(acc[ms][ns][0], acc[ms][ns][1]);
            *(float2*)(sg + (m + 8) * SGST + nn) = make_float2(acc[ms][ns][2], acc[ms][ns][3]);
        }
    }
    __syncthreads();

    // ---- LSTM epilogue: thread = (hid pair, 8 px), all vector ops ----
    int hl2 = tid >> 4;                   // 0..15 pair index
    int px0 = (tid & 15) * 8;             // 0..120
    int qout = mblk * 16 + hl2;
    int yx0  = y0 * 32 + px0;

    float hn2[2][8];
    #pragma unroll
    for (int e = 0; e < 2; e++) {
        int hl  = 2 * hl2 + e;
        int ch  = mblk * 32 + hl;
        float bi  = bias[0 * HID + ch];
        float bfg = bias[1 * HID + ch];
        float bg  = bias[2 * HID + ch];
        float bo  = bias[3 * HID + ch];
        const float* rI = sg + (0 * 32 + hl) * SGST + px0;
        const float* rF = sg + (1 * 32 + hl) * SGST + px0;
        const float* rG = sg + (2 * 32 + hl) * SGST + px0;
        const float* rO = sg + (3 * 32 + hl) * SGST + px0;
        float* cp_ptr = cbuf + (size_t)ch * NPIX + yx0;
        float* op     = out + ((size_t)((n * TT + tcur) * 2 * HID) + dir * HID + ch) * NPIX + yx0;
        #pragma unroll
        for (int v = 0; v < 2; v++) {
            float4 gI = *(const float4*)(rI + v * 4);
            float4 gF = *(const float4*)(rF + v * 4);
            float4 gG = *(const float4*)(rG + v * 4);
            float4 gO = *(const float4*)(rO + v * 4);
            float4 cv = make_float4(0, 0, 0, 0);
            if (t > 0) cv = *(const float4*)(cp_ptr + v * 4);
            float ig[4] = {gI.x + bi,  gI.y + bi,  gI.z + bi,  gI.w + bi};
            float fg[4] = {gF.x + bfg, gF.y + bfg, gF.z + bfg, gF.w + bfg};
            float gg[4] = {gG.x + bg,  gG.y + bg,  gG.z + bg,  gG.w + bg};
            float og[4] = {gO.x + bo,  gO.y + bo,  gO.z + bo,  gO.w + bo};
            float cold[4] = {cv.x, cv.y, cv.z, cv.w};
            float4 cnew, hnew;
            float* cn4 = (float*)&cnew;
            float* hn4 = (float*)&hnew;
            #pragma unroll
            for (int p = 0; p < 4; p++) {
                float cn = sigf(fg[p]) * cold[p] + sigf(ig[p]) * tanh_fast(gg[p]);
                float hn = sigf(og[p]) * tanh_fast(cn);
                cn4[p] = cn;
                hn4[p] = hn;
                hn2[e][v * 4 + p] = hn;
            }
            *(float4*)(cp_ptr + v * 4) = cnew;
            *(float4*)(op + v * 4)     = hnew;
        }
    }
    // packed fp16 h write (B-ready ci-pair words)
    uint32_t hw[8];
    #pragma unroll
    for (int p = 0; p < 8; p++) hw[p] = packh2(hn2[0][p], hn2[1][p]);
    uint32_t* hp = hpout + (size_t)qout * NPIX + yx0;
    *(uint4*)(hp)     = *(uint4*)(hw);
    *(uint4*)(hp + 4) = *(uint4*)(hw + 4);
}

// ---------------------------------------------------------------------------
extern "C" void kernel_launch(void* const* d_in, const int* in_sizes, int n_in,
                              void* d_out, int out_size)
{
    const float* x      = (const float*)d_in[0];
    const float* w_ih_f = (const float*)d_in[1];
    const float* w_hh_f = (const float*)d_in[2];
    const float* b_f    = (const float*)d_in[3];
    const float* w_ih_b = (const float*)d_in[4];
    const float* w_hh_b = (const float*)d_in[5];
    const float* b_b    = (const float*)d_in[6];
    float* out = (float*)d_out;

    cudaFuncSetAttribute(lstm_step, cudaFuncAttributeMaxDynamicSharedMemorySize,
                         (int)SMEM_STEP);

    prep_w_kernel<<<848, 256>>>(w_ih_f, w_hh_f, w_ih_b, w_hh_b);
    for (int t = 0; t < TT; t++)
        lstm_step<<<256, 256, SMEM_STEP>>>(x, b_f, b_b, out, t);
}